// round 15
// baseline (speedup 1.0000x reference)
#include <cuda_runtime.h>
#include <cuda_fp16.h>
#include <math.h>
#include <stdint.h>

#define N_NODES 20000
#define E_EDGES 320000
#define ET      (E_EDGES + N_NODES)   /* 340000 with self loops */
#define IN_DIM  768
#define HID     256
#define H1      3
#define F1      (H1 * HID)            /* 768 */
#define KDIM    768
#define NBLK    ((N_NODES + 255) / 256)   /* 79 */
#define NPERS   296                   /* 2 CTAs x 148 SMs */

/* ---------------- scratch (device globals, no allocs allowed) ------------- */
__device__ __half g_xp1h[(size_t)N_NODES * F1];    /* GEMM1 out (fp16)   */
__device__ __half g_xp2h[(size_t)N_NODES * HID];   /* GEMM2 out (fp16)   */
__device__ __half gx_h [(size_t)N_NODES * IN_DIM]; /* x in fp16          */
__device__ __half g_hh [(size_t)N_NODES * F1];     /* h in fp16          */
__device__ __half gw1t_h[F1 * KDIM];               /* W1^T [n][k] fp16   */
__device__ __half gw2t_h[HID * KDIM];
__device__ float g_asrc1[N_NODES * H1];
__device__ float g_adst1[N_NODES * H1];
__device__ float g_asrc2[N_NODES];
__device__ float g_adst2[N_NODES];
__device__ int   g_deg[N_NODES];
__device__ int   g_rowptr[N_NODES + 1];
__device__ int   g_cursor[N_NODES];
__device__ int   g_col[ET];
__device__ int   g_bsum[128];
__device__ int   g_boff[128];
__device__ int   g_is64;

/* ---------------- helpers ------------------------------------------------- */
__device__ __forceinline__ float warpSum(float v) {
    #pragma unroll
    for (int o = 16; o; o >>= 1) v += __shfl_xor_sync(0xffffffffu, v, o);
    return v;
}
__device__ __forceinline__ uint32_t smem_u32(const void* p) {
    uint32_t a;
    asm("{ .reg .u64 t; cvta.to.shared.u64 t, %1; cvt.u32.u64 %0, t; }"
        : "=r"(a) : "l"(p));
    return a;
}

/* ---------------- mma.sync / ldmatrix / cp.async wrappers ----------------- */
__device__ __forceinline__ void ldsm_x4(uint32_t* r, uint32_t addr) {
    asm volatile("ldmatrix.sync.aligned.m8n8.x4.shared.b16 {%0,%1,%2,%3}, [%4];"
        : "=r"(r[0]), "=r"(r[1]), "=r"(r[2]), "=r"(r[3]) : "r"(addr));
}
__device__ __forceinline__ void mma_f16(float* c, const uint32_t* a, const uint32_t* b) {
    asm volatile(
        "mma.sync.aligned.m16n8k16.row.col.f32.f16.f16.f32 "
        "{%0,%1,%2,%3}, {%4,%5,%6,%7}, {%8,%9}, {%0,%1,%2,%3};"
        : "+f"(c[0]), "+f"(c[1]), "+f"(c[2]), "+f"(c[3])
        : "r"(a[0]), "r"(a[1]), "r"(a[2]), "r"(a[3]), "r"(b[0]), "r"(b[1]));
}
__device__ __forceinline__ void cp16(uint32_t dst, const void* src, int sz) {
    asm volatile("cp.async.cg.shared.global [%0], [%1], 16, %2;"
        :: "r"(dst), "l"(src), "r"(sz) : "memory");
}
__device__ __forceinline__ void cp_commit() {
    asm volatile("cp.async.commit_group;" ::: "memory");
}
template <int W> __device__ __forceinline__ void cp_wait() {
    asm volatile("cp.async.wait_group %0;" :: "n"(W) : "memory");
}

/* ======================================================================== */
/*  Persistent HMMA GEMM (fp16): Ch[M,N] = A[M,768] @ Bt[N,768]^T            */
/*  CTA tile 64x128, BK=128, 2-stage cp.async, warp tile 32x32               */
/*  Fused attention dot-product epilogue (atomics)                           */
/* ======================================================================== */
#define TM    64
#define BK    128
#define LDA   136                  /* fp16 elems per row: 272 B, stride 4 mod 32 */
#define SA_B  (TM * LDA * 2)       /* 17408 B */
#define SB_B  (128 * LDA * 2)      /* 34816 B */
#define STG_B (SA_B + SB_B)        /* 52224 B per stage */
#define NSTG  2
#define GSMEM (NSTG * STG_B)       /* 104448 B */
#define NCHUNK (KDIM / BK)         /* 6 */

__global__ __launch_bounds__(256, 2)
void mma_gemm_kernel(const __half* __restrict__ Ah,
                     const __half* __restrict__ Bh,
                     __half* __restrict__ Ch,
                     const float* __restrict__ att_s,
                     const float* __restrict__ att_d,
                     float* __restrict__ asrc,
                     float* __restrict__ adst,
                     int H, int M, int N, int nTilesX, int nTiles) {
    extern __shared__ char smem[];
    const int t = threadIdx.x, lane = t & 31, wid = t >> 5;
    const int wm = wid >> 2, wn = wid & 3;    /* wm 0..1 rows, wn 0..3 cols */
    const uint32_t sb = smem_u32(smem);
    const int g = lane >> 2, tq = lane & 3;

    /* loader mapping (16 threads per 256B row segment of 16B each) */
    const int lrow = t >> 4;        /* 0..15 */
    const int lcol = (t & 15) * 8;  /* fp16 col, 0..120 */

    for (int tile = blockIdx.x; tile < nTiles; tile += gridDim.x) {
        const int rowBase = (tile / nTilesX) * TM;
        const int colBase = (tile % nTilesX) * 128;

        /* A: 64 rows -> 4 segments of 16 rows; B: 128 rows -> 8 segments */
        int av[4];
        #pragma unroll
        for (int i = 0; i < 4; i++)
            av[i] = (rowBase + lrow + 16 * i) < M ? 16 : 0;
        const __half* pA = Ah + (size_t)(rowBase + lrow) * KDIM + lcol;
        const __half* pB = Bh + (size_t)(colBase + lrow) * KDIM + lcol;
        const uint32_t dA = (uint32_t)(lrow * LDA + lcol) * 2;
        const uint32_t dB = dA + SA_B;

        float acc[2][4][4];
        #pragma unroll
        for (int i = 0; i < 2; i++)
            #pragma unroll
            for (int j = 0; j < 4; j++)
                #pragma unroll
                for (int q = 0; q < 4; q++) acc[i][j][q] = 0.f;

        /* prologue: chunk 0 -> stage 0 */
        {
            const uint32_t b = sb;
            #pragma unroll
            for (int i = 0; i < 4; i++)
                cp16(b + dA + i * (16 * LDA * 2), pA + (size_t)(16 * i) * KDIM, av[i]);
            #pragma unroll
            for (int i = 0; i < 8; i++)
                cp16(b + dB + i * (16 * LDA * 2), pB + (size_t)(16 * i) * KDIM, 16);
            cp_commit();
        }

        for (int c = 0; c < NCHUNK; c++) {
            cp_wait<0>();
            __syncthreads();

            if (c + 1 < NCHUNK) {
                const int k0 = (c + 1) * BK;
                const uint32_t b = sb + ((c + 1) & 1) * STG_B;
                #pragma unroll
                for (int i = 0; i < 4; i++)
                    cp16(b + dA + i * (16 * LDA * 2), pA + k0 + (size_t)(16 * i) * KDIM, av[i]);
                #pragma unroll
                for (int i = 0; i < 8; i++)
                    cp16(b + dB + i * (16 * LDA * 2), pB + k0 + (size_t)(16 * i) * KDIM, 16);
                cp_commit();
            }

            const uint32_t sA = sb + (c & 1) * STG_B;
            const uint32_t sB = sA + SA_B;

            #pragma unroll
            for (int ks = 0; ks < 8; ks++) {
                const int kk = ks * 16;
                uint32_t ah[2][4];
                {
                    const int r  = wm * 32 + (lane & 15);
                    const int kc = kk + ((lane >> 4) << 3);
                    #pragma unroll
                    for (int mt = 0; mt < 2; mt++)
                        ldsm_x4(ah[mt], sA + (uint32_t)((r + mt * 16) * LDA + kc) * 2);
                }
                #pragma unroll
                for (int p = 0; p < 2; p++) {
                    uint32_t bb[4];
                    const int row = wn * 32 + p * 16 + ((lane >> 4) << 3) + (lane & 7);
                    const int kc  = kk + (((lane >> 3) & 1) << 3);
                    ldsm_x4(bb, sB + (uint32_t)(row * LDA + kc) * 2);
                    #pragma unroll
                    for (int mt = 0; mt < 2; mt++) {
                        mma_f16(acc[mt][2 * p],     ah[mt], bb);
                        mma_f16(acc[mt][2 * p + 1], ah[mt], bb + 2);
                    }
                }
            }
        }

        /* ---- epilogue: fp16 store + fused attention dot products --------- */
        const int h = (H > 1) ? (colBase >> 8) : 0;

        float s_c[8], d_c[8];
        #pragma unroll
        for (int nt = 0; nt < 4; nt++) {
            int colg = colBase + wn * 32 + nt * 8 + 2 * tq;
            s_c[2 * nt]     = att_s[colg];
            s_c[2 * nt + 1] = att_s[colg + 1];
            d_c[2 * nt]     = att_d[colg];
            d_c[2 * nt + 1] = att_d[colg + 1];
        }

        #pragma unroll
        for (int mt = 0; mt < 2; mt++) {
            int r0g = rowBase + wm * 32 + mt * 16 + g;
            float ps0 = 0.f, pd0 = 0.f, ps1 = 0.f, pd1 = 0.f;
            #pragma unroll
            for (int nt = 0; nt < 4; nt++) {
                int col = colBase + wn * 32 + nt * 8 + 2 * tq;
                if (r0g < M)
                    *(__half2*)&Ch[(size_t)r0g * N + col] =
                        __floats2half2_rn(acc[mt][nt][0], acc[mt][nt][1]);
                if (r0g + 8 < M)
                    *(__half2*)&Ch[(size_t)(r0g + 8) * N + col] =
                        __floats2half2_rn(acc[mt][nt][2], acc[mt][nt][3]);
                ps0 += acc[mt][nt][0] * s_c[2 * nt] + acc[mt][nt][1] * s_c[2 * nt + 1];
                pd0 += acc[mt][nt][0] * d_c[2 * nt] + acc[mt][nt][1] * d_c[2 * nt + 1];
                ps1 += acc[mt][nt][2] * s_c[2 * nt] + acc[mt][nt][3] * s_c[2 * nt + 1];
                pd1 += acc[mt][nt][2] * d_c[2 * nt] + acc[mt][nt][3] * d_c[2 * nt + 1];
            }
            #pragma unroll
            for (int o = 1; o <= 2; o <<= 1) {
                ps0 += __shfl_xor_sync(0xffffffffu, ps0, o);
                pd0 += __shfl_xor_sync(0xffffffffu, pd0, o);
                ps1 += __shfl_xor_sync(0xffffffffu, ps1, o);
                pd1 += __shfl_xor_sync(0xffffffffu, pd1, o);
            }
            if (tq == 0) {
                if (r0g < M) {
                    atomicAdd(&asrc[r0g * H + h], ps0);
                    atomicAdd(&adst[r0g * H + h], pd0);
                }
                if (r0g + 8 < M) {
                    atomicAdd(&asrc[(r0g + 8) * H + h], ps1);
                    atomicAdd(&adst[(r0g + 8) * H + h], pd1);
                }
            }
        }
    }
}

/* ---------------- fp32 -> fp16 elementwise --------------------------------- */
__global__ void conv_half_kernel(const float* __restrict__ src,
                                 __half* __restrict__ dst, int n4) {
    int i = blockIdx.x * blockDim.x + threadIdx.x;
    if (i >= n4) return;
    float4 v = ((const float4*)src)[i];
    __half2 a = __floats2half2_rn(v.x, v.y);
    __half2 b = __floats2half2_rn(v.z, v.w);
    ((uint2*)dst)[i] = make_uint2(*(uint32_t*)&a, *(uint32_t*)&b);
}

/* ---------------- W[k][n] -> Wt[n][k] transpose -> fp16 -------------------- */
__global__ void trans_half_kernel(const float* __restrict__ W,
                                  __half* __restrict__ Th, int K, int N) {
    __shared__ float tile[32][33];
    int k0 = blockIdx.y * 32, n0 = blockIdx.x * 32;
    int tx = threadIdx.x, ty = threadIdx.y;   /* 32 x 8 */
    #pragma unroll
    for (int i = 0; i < 32; i += 8)
        tile[ty + i][tx] = W[(size_t)(k0 + ty + i) * N + n0 + tx];
    __syncthreads();
    #pragma unroll
    for (int i = 0; i < 32; i += 8) {
        float v = tile[tx][ty + i];
        Th[(size_t)(n0 + ty + i) * K + k0 + tx] = __float2half_rn(v);
    }
}

/* ---------------- init: zero deg + att accumulators + detect dtype --------- */
__global__ void init_kernel(const int* ei32) {
    int i = blockIdx.x * 256 + threadIdx.x;
    if (i < N_NODES) g_deg[i] = 0;
    for (int j = i; j < N_NODES * H1; j += NBLK * 256) {
        g_asrc1[j] = 0.f;
        g_adst1[j] = 0.f;
    }
    if (i < N_NODES) {
        g_asrc2[i] = 0.f;
        g_adst2[i] = 0.f;
    }
    if (blockIdx.x == 0) {
        __shared__ int any;
        if (threadIdx.x == 0) any = 0;
        __syncthreads();
        int v = 0;
        for (int j = threadIdx.x; j < 1024; j += 256)
            v |= ei32[2 * j + 1];
        if (v) atomicOr(&any, 1);
        __syncthreads();
        if (threadIdx.x == 0) g_is64 = (any == 0) ? 1 : 0;
    }
}
__device__ __forceinline__ int edge_at(const void* ei, long long idx) {
    if (g_is64) return (int)((const long long*)ei)[idx];
    return ((const int*)ei)[idx];
}

/* ---------------- CSR build ------------------------------------------------ */
__global__ void count_kernel(const void* ei) {
    int e = blockIdx.x * blockDim.x + threadIdx.x;
    if (e >= ET) return;
    int d = (e < E_EDGES) ? edge_at(ei, (long long)E_EDGES + e) : (e - E_EDGES);
    atomicAdd(&g_deg[d], 1);
}
__global__ void bsum_kernel() {
    __shared__ int s[256];
    int i = blockIdx.x * 256 + threadIdx.x;
    s[threadIdx.x] = (i < N_NODES) ? g_deg[i] : 0;
    __syncthreads();
    for (int o = 128; o; o >>= 1) {
        if (threadIdx.x < o) s[threadIdx.x] += s[threadIdx.x + o];
        __syncthreads();
    }
    if (threadIdx.x == 0) g_bsum[blockIdx.x] = s[0];
}
__global__ void bscan_kernel() {
    __shared__ int s[128];
    int t = threadIdx.x;
    int v = (t < NBLK) ? g_bsum[t] : 0;
    s[t] = v;
    __syncthreads();
    for (int o = 1; o < 128; o <<= 1) {
        int u = (t >= o) ? s[t - o] : 0;
        __syncthreads();
        s[t] += u;
        __syncthreads();
    }
    g_boff[t] = s[t] - v;
    if (t == 0) g_rowptr[N_NODES] = ET;
}
__global__ void fscan_kernel() {
    __shared__ int s[256];
    int t = threadIdx.x;
    int i = blockIdx.x * 256 + t;
    int d = (i < N_NODES) ? g_deg[i] : 0;
    s[t] = d;
    __syncthreads();
    for (int o = 1; o < 256; o <<= 1) {
        int u = (t >= o) ? s[t - o] : 0;
        __syncthreads();
        s[t] += u;
        __syncthreads();
    }
    if (i < N_NODES) {
        int off = s[t] - d + g_boff[blockIdx.x];
        g_rowptr[i] = off;
        g_cursor[i] = off;
    }
}
__global__ void scatter_kernel(const void* ei) {
    int e = blockIdx.x * blockDim.x + threadIdx.x;
    if (e >= ET) return;
    int s, d;
    if (e < E_EDGES) {
        s = edge_at(ei, e);
        d = edge_at(ei, (long long)E_EDGES + e);
    } else {
        s = d = e - E_EDGES;
    }
    int slot = atomicAdd(&g_cursor[d], 1);
    g_col[slot] = s;
}

/* ======================================================================== */
/*  Fused softmax + aggregation, layer 1 (3 heads). Warp per node.          */
/* ======================================================================== */
__global__ __launch_bounds__(256)
void fused_agg1_kernel(const float* __restrict__ b1) {
    __shared__ float sw0[8][128];
    __shared__ float sw1[8][128];
    __shared__ float sw2[8][128];
    __shared__ int   scl[8][128];
    int wrp = threadIdx.x >> 5;
    int n = blockIdx.x * 8 + wrp;
    if (n >= N_NODES) return;
    int lane = threadIdx.x & 31;
    int st = g_rowptr[n], en = g_rowptr[n + 1];
    int deg = en - st;

    float ad0 = g_adst1[n * 3 + 0];
    float ad1 = g_adst1[n * 3 + 1];
    float ad2 = g_adst1[n * 3 + 2];

    float s0 = 0.f, s1 = 0.f, s2 = 0.f;
    #pragma unroll
    for (int r = 0; r < 4; r++) {
        int idx = r * 32 + lane;
        if (idx < deg) {
            int col = g_col[st + idx];
            float v0 = g_asrc1[col * 3 + 0] + ad0;
            float v1 = g_asrc1[col * 3 + 1] + ad1;
            float v2 = g_asrc1[col * 3 + 2] + ad2;
            v0 = (v0 > 0.f) ? v0 : 0.2f * v0;
            v1 = (v1 > 0.f) ? v1 : 0.2f * v1;
            v2 = (v2 > 0.f) ? v2 : 0.2f * v2;
            float e0 = __expf(v0), e1 = __expf(v1), e2 = __expf(v2);
            sw0[wrp][idx] = e0;
            sw1[wrp][idx] = e1;
            sw2[wrp][idx] = e2;
            scl[wrp][idx] = col;
            s0 += e0; s1 += e1; s2 += e2;
        }
    }
    for (int idx = 128 + lane; idx < deg; idx += 32) {
        int col = g_col[st + idx];
        float v0 = g_asrc1[col * 3 + 0] + ad0;
        float v1 = g_asrc1[col * 3 + 1] + ad1;
        float v2 = g_asrc1[col * 3 + 2] + ad2;
        v0 = (v0 > 0.f) ? v0 : 0.2f * v0;
        v1 = (v1 > 0.f) ? v1 : 0.2f * v1;
        v2 = (v2 > 0.f) ? v2 : 0.2f * v2;
        s0 += __expf(v0); s1 += __expf(v1); s2 += __expf(v2);
    }
    s0 = warpSum(s0); s1 = warpSum(s1); s2 = warpSum(s2);
    float inv0 = 1.f / s0, inv1 = 1.f / s1, inv2 = 1.f / s2;
    __syncwarp();

    int ch0 = lane * 24;
    int hd0 = ch0 >> 8, hd1 = (ch0 + 8) >> 8, hd2 = (ch0 + 16) >> 8;

    float acc[24];
    #pragma unroll
    for (int i = 0; i < 24; i++) acc[i] = 0.f;

    int degf = deg < 128 ? deg : 128;
    for (int idx = 0; idx < degf; idx++) {
        float w0 = sw0[wrp][idx];
        float w1 = sw1[wrp][idx];
        float w2 = sw2[wrp][idx];
        int  col = scl[wrp][idx];
        float wa = (hd0 == 0) ? w0 : (hd0 == 1) ? w1 : w2;
        float wb = (hd1 == 0) ? w0 : (hd1 == 1) ? w1 : w2;
        float wc = (hd2 == 0) ? w0 : (hd2 == 1) ? w1 : w2;
        const __half* row = g_xp1h + (size_t)col * F1 + ch0;
        uint4 ua = *(const uint4*)(row);
        uint4 ub = *(const uint4*)(row + 8);
        uint4 uc = *(const uint4*)(row + 16);
        float2 f;
        f = __half22float2(*(__half2*)&ua.x); acc[0]  += wa * f.x; acc[1]  += wa * f.y;
        f = __half22float2(*(__half2*)&ua.y); acc[2]  += wa * f.x; acc[3]  += wa * f.y;
        f = __half22float2(*(__half2*)&ua.z); acc[4]  += wa * f.x; acc[5]  += wa * f.y;
        f = __half22float2(*(__half2*)&ua.w); acc[6]  += wa * f.x; acc[7]  += wa * f.y;
        f = __half22float2(*(__half2*)&ub.x); acc[8]  += wb * f.x; acc[9]  += wb * f.y;
        f = __half22float2(*(__half2*)&ub.y); acc[10] += wb * f.x; acc[11] += wb * f.y;
        f = __half22float2(*(__half2*)&ub.z); acc[12] += wb * f.x; acc[13] += wb * f.y;
        f = __half22float2(*(__half2*)&ub.w); acc[14] += wb * f.x; acc[15] += wb * f.y;
        f = __half22float2(*(__half2*)&uc.x); acc[16] += wc * f.x; acc[17] += wc * f.y;
        f = __half22float2(*(__half2*)&uc.y); acc[18] += wc * f.x; acc[19] += wc * f.y;
        f = __half22float2(*(__half2*)&uc.z); acc[20] += wc * f.x; acc[21] += wc * f.y;
        f = __half22float2(*(__half2*)&uc.w); acc[22] += wc * f.x; acc[23] += wc * f.y;
    }
    for (int idx = 128; idx < deg; idx++) {
        int col = g_col[st + idx];
        float v0 = g_asrc1[col * 3 + 0] + ad0;
        float v1 = g_asrc1[col * 3 + 1] + ad1;
        float v2 = g_asrc1[col * 3 + 2] + ad2;
        v0 = (v0 > 0.f) ? v0 : 0.2f * v0;
        v1 = (v1 > 0.f) ? v1 : 0.2f * v1;
        v2 = (v2 > 0.f) ? v2 : 0.2f * v2;
        float w0 = __expf(v0), w1 = __expf(v1), w2 = __expf(v2);
        float wa = (hd0 == 0) ? w0 : (hd0 == 1) ? w1 : w2;
        float wb = (hd1 == 0) ? w0 : (hd1 == 1) ? w1 : w2;
        float wc = (hd2 == 0) ? w0 : (hd2 == 1) ? w1 : w2;
        const __half* row = g_xp1h + (size_t)col * F1 + ch0;
        uint4 ua = *(const uint4*)(row);
        uint4 ub = *(const uint4*)(row + 8);
        uint4 uc = *(const uint4*)(row + 16);
        float2 f;
        f = __half22float2(*(__half2*)&ua.x); acc[0]  += wa * f.x; acc[1]  += wa * f.y;
        f = __half22float2(*(__half2*)&ua.y); acc[2]  += wa * f.x; acc[3]  += wa * f.y;
        f = __half22float2(*(__half2*)&ua.z); acc[4]  += wa * f.x; acc[5]  += wa * f.y;
        f = __half22float2(*(__half2*)&ua.w); acc[6]  += wa * f.x; acc[7]  += wa * f.y;
        f = __half22float2(*(__half2*)&ub.x); acc[8]  += wb * f.x; acc[9]  += wb * f.y;
        f = __half22float2(*(__half2*)&ub.y); acc[10] += wb * f.x; acc[11] += wb * f.y;
        f = __half22float2(*(__half2*)&ub.z); acc[12] += wb * f.x; acc[13] += wb * f.y;
        f = __half22float2(*(__half2*)&ub.w); acc[14] += wb * f.x; acc[15] += wb * f.y;
        f = __half22float2(*(__half2*)&uc.x); acc[16] += wc * f.x; acc[17] += wc * f.y;
        f = __half22float2(*(__half2*)&uc.y); acc[18] += wc * f.x; acc[19] += wc * f.y;
        f = __half22float2(*(__half2*)&uc.z); acc[20] += wc * f.x; acc[21] += wc * f.y;
        f = __half22float2(*(__half2*)&uc.w); acc[22] += wc * f.x; acc[23] += wc * f.y;
    }

    float invv[3];
    invv[0] = (hd0 == 0) ? inv0 : (hd0 == 1) ? inv1 : inv2;
    invv[1] = (hd1 == 0) ? inv0 : (hd1 == 1) ? inv1 : inv2;
    invv[2] = (hd2 == 0) ? inv0 : (hd2 == 1) ? inv1 : inv2;
    __half* outp = g_hh + (size_t)n * F1 + ch0;
    #pragma unroll
    for (int c = 0; c < 3; c++) {
        float inv = invv[c];
        float4 ba = *(const float4*)(b1 + ch0 + c * 8);
        float4 bb = *(const float4*)(b1 + ch0 + c * 8 + 4);
        float o[8];
        o[0] = acc[c*8+0] * inv + ba.x; o[1] = acc[c*8+1] * inv + ba.y;
        o[2] = acc[c*8+2] * inv + ba.z; o[3] = acc[c*8+3] * inv + ba.w;
        o[4] = acc[c*8+4] * inv + bb.x; o[5] = acc[c*8+5] * inv + bb.y;
        o[6] = acc[c*8+6] * inv + bb.z; o[7] = acc[c*8+7] * inv + bb.w;
        #pragma unroll
        for (int i = 0; i < 8; i++)
            o[i] = (o[i] > 0.f) ? o[i] : expm1f(o[i]);
        __half2 h0 = __floats2half2_rn(o[0], o[1]);
        __half2 h1 = __floats2half2_rn(o[2], o[3]);
        __half2 h2 = __floats2half2_rn(o[4], o[5]);
        __half2 h3 = __floats2half2_rn(o[6], o[7]);
        uint4 u;
        u.x = *(uint32_t*)&h0; u.y = *(uint32_t*)&h1;
        u.z = *(uint32_t*)&h2; u.w = *(uint32_t*)&h3;
        *(uint4*)(outp + c * 8) = u;
    }
}

/* ======================================================================== */
/*  Fused softmax + aggregation, layer 2 (1 head). Warp per node.           */
/* ======================================================================== */
__global__ __launch_bounds__(256)
void fused_agg2_kernel(const float* __restrict__ b2, float* __restrict__ out) {
    __shared__ float sw[8][128];
    __shared__ int   scl[8][128];
    int wrp = threadIdx.x >> 5;
    int n = blockIdx.x * 8 + wrp;
    if (n >= N_NODES) return;
    int lane = threadIdx.x & 31;
    int st = g_rowptr[n], en = g_rowptr[n + 1];
    int deg = en - st;

    float ad = g_adst2[n];

    float sum = 0.f;
    #pragma unroll
    for (int r = 0; r < 4; r++) {
        int idx = r * 32 + lane;
        if (idx < deg) {
            int col = g_col[st + idx];
            float v = g_asrc2[col] + ad;
            v = (v > 0.f) ? v : 0.2f * v;
            float e = __expf(v);
            sw[wrp][idx] = e;
            scl[wrp][idx] = col;
            sum += e;
        }
    }
    for (int idx = 128 + lane; idx < deg; idx += 32) {
        int col = g_col[st + idx];
        float v = g_asrc2[col] + ad;
        v = (v > 0.f) ? v : 0.2f * v;
        sum += __expf(v);
    }
    sum = warpSum(sum);
    float inv = 1.f / sum;
    __syncwarp();

    int ch0 = lane * 8;
    float acc[8];
    #pragma unroll
    for (int i = 0; i < 8; i++) acc[i] = 0.f;

    int degf = deg < 128 ? deg : 128;
    for (int idx = 0; idx < degf; idx++) {
        float w  = sw[wrp][idx];
        int  col = scl[wrp][idx];
        uint4 u = *(const uint4*)(g_xp2h + (size_t)col * HID + ch0);
        float2 f0 = __half22float2(*(__half2*)&u.x);
        float2 f1 = __half22float2(*(__half2*)&u.y);
        float2 f2 = __half22float2(*(__half2*)&u.z);
        float2 f3 = __half22float2(*(__half2*)&u.w);
        acc[0] += w * f0.x; acc[1] += w * f0.y;
        acc[2] += w * f1.x; acc[3] += w * f1.y;
        acc[4] += w * f2.x; acc[5] += w * f2.y;
        acc[6] += w * f3.x; acc[7] += w * f3.y;
    }
    for (int idx = 128; idx < deg; idx++) {
        int col = g_col[st + idx];
        float v = g_asrc2[col] + ad;
        v = (v > 0.f) ? v : 0.2f * v;
        float w = __expf(v);
        uint4 u = *(const uint4*)(g_xp2h + (size_t)col * HID + ch0);
        float2 f0 = __half22float2(*(__half2*)&u.x);
        float2 f1 = __half22float2(*(__half2*)&u.y);
        float2 f2 = __half22float2(*(__half2*)&u.z);
        float2 f3 = __half22float2(*(__half2*)&u.w);
        acc[0] += w * f0.x; acc[1] += w * f0.y;
        acc[2] += w * f1.x; acc[3] += w * f1.y;
        acc[4] += w * f2.x; acc[5] += w * f2.y;
        acc[6] += w * f3.x; acc[7] += w * f3.y;
    }

    float4 ba = *(const float4*)(b2 + ch0);
    float4 bb = *(const float4*)(b2 + ch0 + 4);
    float* op = out + (size_t)n * HID + ch0;
    *(float4*)op = make_float4(acc[0] * inv + ba.x, acc[1] * inv + ba.y,
                               acc[2] * inv + ba.z, acc[3] * inv + ba.w);
    *(float4*)(op + 4) = make_float4(acc[4] * inv + bb.x, acc[5] * inv + bb.y,
                                     acc[6] * inv + bb.z, acc[7] * inv + bb.w);
}

/* ---------------- launch --------------------------------------------------- */
extern "C" void kernel_launch(void* const* d_in, const int* in_sizes, int n_in,
                              void* d_out, int out_size) {
    const float* x   = (const float*)d_in[0];
    const void*  ei  = d_in[1];
    const float* W1  = (const float*)d_in[2];
    const float* as1 = (const float*)d_in[3];
    const float* ad1 = (const float*)d_in[4];
    const float* b1  = (const float*)d_in[5];
    const float* W2  = (const float*)d_in[6];
    const float* as2 = (const float*)d_in[7];
    const float* ad2 = (const float*)d_in[8];
    const float* b2  = (const float*)d_in[9];
    float* out = (float*)d_out;

    void *p_x1h, *p_x2h, *p_as1, *p_ad1, *p_as2, *p_ad2;
    void *p_xh, *p_hh, *p_w1h, *p_w2h;
    cudaGetSymbolAddress(&p_x1h, g_xp1h);
    cudaGetSymbolAddress(&p_x2h, g_xp2h);
    cudaGetSymbolAddress(&p_as1, g_asrc1);
    cudaGetSymbolAddress(&p_ad1, g_adst1);
    cudaGetSymbolAddress(&p_as2, g_asrc2);
    cudaGetSymbolAddress(&p_ad2, g_adst2);
    cudaGetSymbolAddress(&p_xh,  gx_h);
    cudaGetSymbolAddress(&p_hh,  g_hh);
    cudaGetSymbolAddress(&p_w1h, gw1t_h);
    cudaGetSymbolAddress(&p_w2h, gw2t_h);

    cudaFuncSetAttribute(mma_gemm_kernel,
                         cudaFuncAttributeMaxDynamicSharedMemorySize, GSMEM);

    /* #1..#3: prerequisites of GEMM1 */
    {
        int n4 = N_NODES * IN_DIM / 4;
        conv_half_kernel<<<(n4 + 255) / 256, 256>>>(x, (__half*)p_xh, n4);
        trans_half_kernel<<<dim3(F1 / 32, KDIM / 32), dim3(32, 8)>>>(
            W1, (__half*)p_w1h, KDIM, F1);
    }
    init_kernel<<<NBLK, 256>>>((const int*)ei);

    /* #4: GEMM1 + fused attention, persistent (ncu capture target) */
    {
        int nTilesX = F1 / 128;                          /* 6 */
        int nTiles  = nTilesX * ((N_NODES + TM - 1) / TM);   /* 6*313 */
        int grid = nTiles < NPERS ? nTiles : NPERS;
        mma_gemm_kernel<<<grid, 256, GSMEM>>>(
            (const __half*)p_xh, (const __half*)p_w1h,
            (__half*)p_x1h, as1, ad1, (float*)p_as1, (float*)p_ad1,
            H1, N_NODES, F1, nTilesX, nTiles);
    }

    /* CSR build + W2 prep (independent of GEMM1) */
    trans_half_kernel<<<dim3(HID / 32, KDIM / 32), dim3(32, 8)>>>(
        W2, (__half*)p_w2h, KDIM, HID);
    count_kernel<<<(ET + 255) / 256, 256>>>(ei);
    bsum_kernel<<<NBLK, 256>>>();
    bscan_kernel<<<1, 128>>>();
    fscan_kernel<<<NBLK, 256>>>();
    scatter_kernel<<<(ET + 255) / 256, 256>>>(ei);

    /* layer 1 edge phase: fused softmax + aggregation */
    fused_agg1_kernel<<<(N_NODES + 7) / 8, 256>>>(b1);

    /* layer 2 */
    {
        int nTilesX = HID / 128;                         /* 2 */
        int nTiles  = nTilesX * ((N_NODES + TM - 1) / TM);   /* 2*313 */
        int grid = nTiles < NPERS ? nTiles : NPERS;
        mma_gemm_kernel<<<grid, 256, GSMEM>>>(
            (const __half*)p_hh, (const __half*)p_w2h,
            (__half*)p_x2h, as2, ad2, (float*)p_as2, (float*)p_ad2,
            1, N_NODES, HID, nTilesX, nTiles);
    }
    fused_agg2_kernel<<<(N_NODES + 7) / 8, 256>>>(b2, out);
}

// round 16
// speedup vs baseline: 1.0522x; 1.0522x over previous
#include <cuda_runtime.h>
#include <cuda_fp16.h>
#include <math.h>
#include <stdint.h>

#define N_NODES 20000
#define E_EDGES 320000
#define ET      (E_EDGES + N_NODES)   /* 340000 with self loops */
#define IN_DIM  768
#define HID     256
#define H1      3
#define F1      (H1 * HID)            /* 768 */
#define KDIM    768
#define NBLK    ((N_NODES + 255) / 256)   /* 79 */
#define NPERS   296                   /* 2 CTAs x 148 SMs */

/* ---------------- scratch (device globals, no allocs allowed) ------------- */
__device__ __half g_xp1h[(size_t)N_NODES * F1];    /* GEMM1 out (fp16)   */
__device__ __half g_xp2h[(size_t)N_NODES * HID];   /* GEMM2 out (fp16)   */
__device__ __half gx_h [(size_t)N_NODES * IN_DIM]; /* x in fp16          */
__device__ __half g_hh [(size_t)N_NODES * F1];     /* h in fp16          */
__device__ __half gw1t_h[F1 * KDIM];               /* W1^T [n][k] fp16   */
__device__ __half gw2t_h[HID * KDIM];
__device__ float g_asrc1[N_NODES * H1];
__device__ float g_adst1[N_NODES * H1];
__device__ float g_asrc2[N_NODES];
__device__ float g_adst2[N_NODES];
__device__ int   g_deg[N_NODES];
__device__ int   g_rowptr[N_NODES + 1];
__device__ int   g_cursor[N_NODES];
__device__ int   g_col[ET];
__device__ int   g_bsum[128];
__device__ int   g_boff[128];
__device__ int   g_is64;

/* ---------------- helpers ------------------------------------------------- */
__device__ __forceinline__ float warpSum(float v) {
    #pragma unroll
    for (int o = 16; o; o >>= 1) v += __shfl_xor_sync(0xffffffffu, v, o);
    return v;
}
__device__ __forceinline__ uint32_t smem_u32(const void* p) {
    uint32_t a;
    asm("{ .reg .u64 t; cvta.to.shared.u64 t, %1; cvt.u32.u64 %0, t; }"
        : "=r"(a) : "l"(p));
    return a;
}

/* ---------------- mma.sync / ldmatrix / cp.async wrappers ----------------- */
__device__ __forceinline__ void ldsm_x4(uint32_t* r, uint32_t addr) {
    asm volatile("ldmatrix.sync.aligned.m8n8.x4.shared.b16 {%0,%1,%2,%3}, [%4];"
        : "=r"(r[0]), "=r"(r[1]), "=r"(r[2]), "=r"(r[3]) : "r"(addr));
}
__device__ __forceinline__ void mma_f16(float* c, const uint32_t* a, const uint32_t* b) {
    asm volatile(
        "mma.sync.aligned.m16n8k16.row.col.f32.f16.f16.f32 "
        "{%0,%1,%2,%3}, {%4,%5,%6,%7}, {%8,%9}, {%0,%1,%2,%3};"
        : "+f"(c[0]), "+f"(c[1]), "+f"(c[2]), "+f"(c[3])
        : "r"(a[0]), "r"(a[1]), "r"(a[2]), "r"(a[3]), "r"(b[0]), "r"(b[1]));
}
__device__ __forceinline__ void cp16(uint32_t dst, const void* src, int sz) {
    asm volatile("cp.async.cg.shared.global [%0], [%1], 16, %2;"
        :: "r"(dst), "l"(src), "r"(sz) : "memory");
}
__device__ __forceinline__ void cp_commit() {
    asm volatile("cp.async.commit_group;" ::: "memory");
}
template <int W> __device__ __forceinline__ void cp_wait() {
    asm volatile("cp.async.wait_group %0;" :: "n"(W) : "memory");
}

/* ======================================================================== */
/*  Persistent HMMA GEMM (fp16): Ch[M,N] = A[M,768] @ Bt[N,768]^T            */
/*  CTA tile 128x128, BK=64, 3-stage cp.async, 1 barrier/chunk, ldsm_x4      */
/*  Fused attention dot-product epilogue (atomics)    [R13 configuration]    */
/* ======================================================================== */
#define BK    64
#define LDA   72                   /* 144 B rows: bank stride 4 mod 32 */
#define TILE_AB (128 * LDA * 2)    /* 18432 B per tile array */
#define STG_B  (2 * TILE_AB)       /* 36864 B per stage (A + B) */
#define NSTG   3
#define GSMEM  (NSTG * STG_B)      /* 110592 B */
#define NCHUNK (KDIM / BK)         /* 12 */

__global__ __launch_bounds__(256, 2)
void mma_gemm_kernel(const __half* __restrict__ Ah,
                     const __half* __restrict__ Bh,
                     __half* __restrict__ Ch,
                     const float* __restrict__ att_s,
                     const float* __restrict__ att_d,
                     float* __restrict__ asrc,
                     float* __restrict__ adst,
                     int H, int M, int N, int nTilesX, int nTiles) {
    extern __shared__ char smem[];
    const int t = threadIdx.x, lane = t & 31, wid = t >> 5;
    const int wm = wid >> 2, wn = wid & 3;
    const uint32_t sb = smem_u32(smem);

    const int rbase = t >> 3;            /* 0..31 */
    const int cs    = (t & 7) * 8;       /* fp16 col offset, 0..56 */
    const uint32_t dd = (uint32_t)(rbase * LDA + cs) * 2;
    const int g = lane >> 2, tq = lane & 3;

    for (int tile = blockIdx.x; tile < nTiles; tile += gridDim.x) {
        const int rowBase = (tile / nTilesX) * 128;
        const int colBase = (tile % nTilesX) * 128;

        int av[4];
        #pragma unroll
        for (int i = 0; i < 4; i++)
            av[i] = (rowBase + rbase + 32 * i) < M ? 16 : 0;
        const __half* pA = Ah + (size_t)(rowBase + rbase) * KDIM + cs;
        const __half* pB = Bh + (size_t)(colBase + rbase) * KDIM + cs;

        float acc[4][4][4];
        #pragma unroll
        for (int i = 0; i < 4; i++)
            #pragma unroll
            for (int j = 0; j < 4; j++)
                #pragma unroll
                for (int q = 0; q < 4; q++) acc[i][j][q] = 0.f;

        /* prologue: chunks 0,1 -> stages 0,1 */
        #pragma unroll
        for (int p = 0; p < 2; p++) {
            const uint32_t b = sb + p * STG_B;
            const int k0 = p * BK;
            #pragma unroll
            for (int i = 0; i < 4; i++) {
                cp16(b + dd + i * (32 * LDA * 2), pA + k0 + (size_t)(32 * i) * KDIM, av[i]);
                cp16(b + TILE_AB + dd + i * (32 * LDA * 2), pB + k0 + (size_t)(32 * i) * KDIM, 16);
            }
            cp_commit();
        }

        for (int c = 0; c < NCHUNK; c++) {
            if (c < NCHUNK - 1) cp_wait<1>();
            else                cp_wait<0>();
            __syncthreads();

            if (c + 2 < NCHUNK) {
                const int k0 = (c + 2) * BK;
                const uint32_t b = sb + ((c + 2) % NSTG) * STG_B;
                #pragma unroll
                for (int i = 0; i < 4; i++) {
                    cp16(b + dd + i * (32 * LDA * 2), pA + k0 + (size_t)(32 * i) * KDIM, av[i]);
                    cp16(b + TILE_AB + dd + i * (32 * LDA * 2), pB + k0 + (size_t)(32 * i) * KDIM, 16);
                }
                cp_commit();
            }

            const uint32_t sA = sb + (c % NSTG) * STG_B;
            const uint32_t sB = sA + TILE_AB;

            #pragma unroll
            for (int ks = 0; ks < 4; ks++) {
                const int kk = ks * 16;
                uint32_t ah[4][4];
                {
                    const int r  = wm * 64 + (lane & 15);
                    const int kc = kk + ((lane >> 4) << 3);
                    #pragma unroll
                    for (int mt = 0; mt < 4; mt++)
                        ldsm_x4(ah[mt], sA + (uint32_t)((r + mt * 16) * LDA + kc) * 2);
                }
                #pragma unroll
                for (int p = 0; p < 2; p++) {
                    uint32_t bb[4];
                    const int row = wn * 32 + p * 16 + ((lane >> 4) << 3) + (lane & 7);
                    const int kc  = kk + (((lane >> 3) & 1) << 3);
                    ldsm_x4(bb, sB + (uint32_t)(row * LDA + kc) * 2);
                    #pragma unroll
                    for (int mt = 0; mt < 4; mt++) {
                        mma_f16(acc[mt][2 * p],     ah[mt], bb);
                        mma_f16(acc[mt][2 * p + 1], ah[mt], bb + 2);
                    }
                }
            }
        }

        /* ---- epilogue: fp16 store + fused attention dot products --------- */
        const int h = (H > 1) ? (colBase >> 8) : 0;

        float s_c[8], d_c[8];
        #pragma unroll
        for (int nt = 0; nt < 4; nt++) {
            int colg = colBase + wn * 32 + nt * 8 + 2 * tq;
            s_c[2 * nt]     = att_s[colg];
            s_c[2 * nt + 1] = att_s[colg + 1];
            d_c[2 * nt]     = att_d[colg];
            d_c[2 * nt + 1] = att_d[colg + 1];
        }

        #pragma unroll
        for (int mt = 0; mt < 4; mt++) {
            int r0g = rowBase + wm * 64 + mt * 16 + g;
            float ps0 = 0.f, pd0 = 0.f, ps1 = 0.f, pd1 = 0.f;
            #pragma unroll
            for (int nt = 0; nt < 4; nt++) {
                int col = colBase + wn * 32 + nt * 8 + 2 * tq;
                if (r0g < M)
                    *(__half2*)&Ch[(size_t)r0g * N + col] =
                        __floats2half2_rn(acc[mt][nt][0], acc[mt][nt][1]);
                if (r0g + 8 < M)
                    *(__half2*)&Ch[(size_t)(r0g + 8) * N + col] =
                        __floats2half2_rn(acc[mt][nt][2], acc[mt][nt][3]);
                ps0 += acc[mt][nt][0] * s_c[2 * nt] + acc[mt][nt][1] * s_c[2 * nt + 1];
                pd0 += acc[mt][nt][0] * d_c[2 * nt] + acc[mt][nt][1] * d_c[2 * nt + 1];
                ps1 += acc[mt][nt][2] * s_c[2 * nt] + acc[mt][nt][3] * s_c[2 * nt + 1];
                pd1 += acc[mt][nt][2] * d_c[2 * nt] + acc[mt][nt][3] * d_c[2 * nt + 1];
            }
            #pragma unroll
            for (int o = 1; o <= 2; o <<= 1) {
                ps0 += __shfl_xor_sync(0xffffffffu, ps0, o);
                pd0 += __shfl_xor_sync(0xffffffffu, pd0, o);
                ps1 += __shfl_xor_sync(0xffffffffu, ps1, o);
                pd1 += __shfl_xor_sync(0xffffffffu, pd1, o);
            }
            if (tq == 0) {
                if (r0g < M) {
                    atomicAdd(&asrc[r0g * H + h], ps0);
                    atomicAdd(&adst[r0g * H + h], pd0);
                }
                if (r0g + 8 < M) {
                    atomicAdd(&asrc[(r0g + 8) * H + h], ps1);
                    atomicAdd(&adst[(r0g + 8) * H + h], pd1);
                }
            }
        }
    }
}

/* ---------------- fp32 -> fp16 elementwise --------------------------------- */
__global__ void conv_half_kernel(const float* __restrict__ src,
                                 __half* __restrict__ dst, int n4) {
    int i = blockIdx.x * blockDim.x + threadIdx.x;
    if (i >= n4) return;
    float4 v = ((const float4*)src)[i];
    __half2 a = __floats2half2_rn(v.x, v.y);
    __half2 b = __floats2half2_rn(v.z, v.w);
    ((uint2*)dst)[i] = make_uint2(*(uint32_t*)&a, *(uint32_t*)&b);
}

/* ---------------- W1 and W2 transpose -> fp16, single launch --------------- */
__global__ void trans_both_kernel(const float* __restrict__ W1f, __half* __restrict__ T1,
                                  const float* __restrict__ W2f, __half* __restrict__ T2) {
    __shared__ float tile[32][33];
    const float* W;
    __half* T;
    int N;
    if (blockIdx.z == 0) { W = W1f; T = T1; N = F1; }
    else                 { W = W2f; T = T2; N = HID; }
    int n0 = blockIdx.x * 32;
    if (n0 >= N) return;
    int k0 = blockIdx.y * 32;
    int tx = threadIdx.x, ty = threadIdx.y;   /* 32 x 8 */
    #pragma unroll
    for (int i = 0; i < 32; i += 8)
        tile[ty + i][tx] = W[(size_t)(k0 + ty + i) * N + n0 + tx];
    __syncthreads();
    #pragma unroll
    for (int i = 0; i < 32; i += 8) {
        float v = tile[tx][ty + i];
        T[(size_t)(n0 + ty + i) * KDIM + k0 + tx] = __float2half_rn(v);
    }
}

/* ---------------- init: zero deg + att accumulators + detect dtype --------- */
__global__ void init_kernel(const int* ei32) {
    int i = blockIdx.x * 256 + threadIdx.x;
    if (i < N_NODES) g_deg[i] = 0;
    for (int j = i; j < N_NODES * H1; j += NBLK * 256) {
        g_asrc1[j] = 0.f;
        g_adst1[j] = 0.f;
    }
    if (i < N_NODES) {
        g_asrc2[i] = 0.f;
        g_adst2[i] = 0.f;
    }
    if (blockIdx.x == 0) {
        __shared__ int any;
        if (threadIdx.x == 0) any = 0;
        __syncthreads();
        int v = 0;
        for (int j = threadIdx.x; j < 1024; j += 256)
            v |= ei32[2 * j + 1];
        if (v) atomicOr(&any, 1);
        __syncthreads();
        if (threadIdx.x == 0) g_is64 = (any == 0) ? 1 : 0;
    }
}
__device__ __forceinline__ int edge_at(const void* ei, long long idx) {
    if (g_is64) return (int)((const long long*)ei)[idx];
    return ((const int*)ei)[idx];
}

/* ---------------- CSR build ------------------------------------------------ */
__global__ void count_kernel(const void* ei) {
    int e = blockIdx.x * blockDim.x + threadIdx.x;
    if (e >= ET) return;
    int d = (e < E_EDGES) ? edge_at(ei, (long long)E_EDGES + e) : (e - E_EDGES);
    atomicAdd(&g_deg[d], 1);
}
__global__ void bsum_kernel() {
    __shared__ int s[256];
    int i = blockIdx.x * 256 + threadIdx.x;
    s[threadIdx.x] = (i < N_NODES) ? g_deg[i] : 0;
    __syncthreads();
    for (int o = 128; o; o >>= 1) {
        if (threadIdx.x < o) s[threadIdx.x] += s[threadIdx.x + o];
        __syncthreads();
    }
    if (threadIdx.x == 0) g_bsum[blockIdx.x] = s[0];
}
__global__ void bscan_kernel() {
    __shared__ int s[128];
    int t = threadIdx.x;
    int v = (t < NBLK) ? g_bsum[t] : 0;
    s[t] = v;
    __syncthreads();
    for (int o = 1; o < 128; o <<= 1) {
        int u = (t >= o) ? s[t - o] : 0;
        __syncthreads();
        s[t] += u;
        __syncthreads();
    }
    g_boff[t] = s[t] - v;
    if (t == 0) g_rowptr[N_NODES] = ET;
}
__global__ void fscan_kernel() {
    __shared__ int s[256];
    int t = threadIdx.x;
    int i = blockIdx.x * 256 + t;
    int d = (i < N_NODES) ? g_deg[i] : 0;
    s[t] = d;
    __syncthreads();
    for (int o = 1; o < 256; o <<= 1) {
        int u = (t >= o) ? s[t - o] : 0;
        __syncthreads();
        s[t] += u;
        __syncthreads();
    }
    if (i < N_NODES) {
        int off = s[t] - d + g_boff[blockIdx.x];
        g_rowptr[i] = off;
        g_cursor[i] = off;
    }
}
__global__ void scatter_kernel(const void* ei) {
    int e = blockIdx.x * blockDim.x + threadIdx.x;
    if (e >= ET) return;
    int s, d;
    if (e < E_EDGES) {
        s = edge_at(ei, e);
        d = edge_at(ei, (long long)E_EDGES + e);
    } else {
        s = d = e - E_EDGES;
    }
    int slot = atomicAdd(&g_cursor[d], 1);
    g_col[slot] = s;
}

/* ======================================================================== */
/*  Fused softmax + aggregation, layer 1 (3 heads). Warp per node.          */
/* ======================================================================== */
__global__ __launch_bounds__(256)
void fused_agg1_kernel(const float* __restrict__ b1) {
    __shared__ float sw0[8][128];
    __shared__ float sw1[8][128];
    __shared__ float sw2[8][128];
    __shared__ int   scl[8][128];
    int wrp = threadIdx.x >> 5;
    int n = blockIdx.x * 8 + wrp;
    if (n >= N_NODES) return;
    int lane = threadIdx.x & 31;
    int st = g_rowptr[n], en = g_rowptr[n + 1];
    int deg = en - st;

    float ad0 = g_adst1[n * 3 + 0];
    float ad1 = g_adst1[n * 3 + 1];
    float ad2 = g_adst1[n * 3 + 2];

    float s0 = 0.f, s1 = 0.f, s2 = 0.f;
    #pragma unroll
    for (int r = 0; r < 4; r++) {
        int idx = r * 32 + lane;
        if (idx < deg) {
            int col = g_col[st + idx];
            float v0 = g_asrc1[col * 3 + 0] + ad0;
            float v1 = g_asrc1[col * 3 + 1] + ad1;
            float v2 = g_asrc1[col * 3 + 2] + ad2;
            v0 = (v0 > 0.f) ? v0 : 0.2f * v0;
            v1 = (v1 > 0.f) ? v1 : 0.2f * v1;
            v2 = (v2 > 0.f) ? v2 : 0.2f * v2;
            float e0 = __expf(v0), e1 = __expf(v1), e2 = __expf(v2);
            sw0[wrp][idx] = e0;
            sw1[wrp][idx] = e1;
            sw2[wrp][idx] = e2;
            scl[wrp][idx] = col;
            s0 += e0; s1 += e1; s2 += e2;
        }
    }
    for (int idx = 128 + lane; idx < deg; idx += 32) {
        int col = g_col[st + idx];
        float v0 = g_asrc1[col * 3 + 0] + ad0;
        float v1 = g_asrc1[col * 3 + 1] + ad1;
        float v2 = g_asrc1[col * 3 + 2] + ad2;
        v0 = (v0 > 0.f) ? v0 : 0.2f * v0;
        v1 = (v1 > 0.f) ? v1 : 0.2f * v1;
        v2 = (v2 > 0.f) ? v2 : 0.2f * v2;
        s0 += __expf(v0); s1 += __expf(v1); s2 += __expf(v2);
    }
    s0 = warpSum(s0); s1 = warpSum(s1); s2 = warpSum(s2);
    float inv0 = 1.f / s0, inv1 = 1.f / s1, inv2 = 1.f / s2;
    __syncwarp();

    int ch0 = lane * 24;
    int hd0 = ch0 >> 8, hd1 = (ch0 + 8) >> 8, hd2 = (ch0 + 16) >> 8;

    float acc[24];
    #pragma unroll
    for (int i = 0; i < 24; i++) acc[i] = 0.f;

    int degf = deg < 128 ? deg : 128;
    for (int idx = 0; idx < degf; idx++) {
        float w0 = sw0[wrp][idx];
        float w1 = sw1[wrp][idx];
        float w2 = sw2[wrp][idx];
        int  col = scl[wrp][idx];
        float wa = (hd0 == 0) ? w0 : (hd0 == 1) ? w1 : w2;
        float wb = (hd1 == 0) ? w0 : (hd1 == 1) ? w1 : w2;
        float wc = (hd2 == 0) ? w0 : (hd2 == 1) ? w1 : w2;
        const __half* row = g_xp1h + (size_t)col * F1 + ch0;
        uint4 ua = *(const uint4*)(row);
        uint4 ub = *(const uint4*)(row + 8);
        uint4 uc = *(const uint4*)(row + 16);
        float2 f;
        f = __half22float2(*(__half2*)&ua.x); acc[0]  += wa * f.x; acc[1]  += wa * f.y;
        f = __half22float2(*(__half2*)&ua.y); acc[2]  += wa * f.x; acc[3]  += wa * f.y;
        f = __half22float2(*(__half2*)&ua.z); acc[4]  += wa * f.x; acc[5]  += wa * f.y;
        f = __half22float2(*(__half2*)&ua.w); acc[6]  += wa * f.x; acc[7]  += wa * f.y;
        f = __half22float2(*(__half2*)&ub.x); acc[8]  += wb * f.x; acc[9]  += wb * f.y;
        f = __half22float2(*(__half2*)&ub.y); acc[10] += wb * f.x; acc[11] += wb * f.y;
        f = __half22float2(*(__half2*)&ub.z); acc[12] += wb * f.x; acc[13] += wb * f.y;
        f = __half22float2(*(__half2*)&ub.w); acc[14] += wb * f.x; acc[15] += wb * f.y;
        f = __half22float2(*(__half2*)&uc.x); acc[16] += wc * f.x; acc[17] += wc * f.y;
        f = __half22float2(*(__half2*)&uc.y); acc[18] += wc * f.x; acc[19] += wc * f.y;
        f = __half22float2(*(__half2*)&uc.z); acc[20] += wc * f.x; acc[21] += wc * f.y;
        f = __half22float2(*(__half2*)&uc.w); acc[22] += wc * f.x; acc[23] += wc * f.y;
    }
    for (int idx = 128; idx < deg; idx++) {
        int col = g_col[st + idx];
        float v0 = g_asrc1[col * 3 + 0] + ad0;
        float v1 = g_asrc1[col * 3 + 1] + ad1;
        float v2 = g_asrc1[col * 3 + 2] + ad2;
        v0 = (v0 > 0.f) ? v0 : 0.2f * v0;
        v1 = (v1 > 0.f) ? v1 : 0.2f * v1;
        v2 = (v2 > 0.f) ? v2 : 0.2f * v2;
        float w0 = __expf(v0), w1 = __expf(v1), w2 = __expf(v2);
        float wa = (hd0 == 0) ? w0 : (hd0 == 1) ? w1 : w2;
        float wb = (hd1 == 0) ? w0 : (hd1 == 1) ? w1 : w2;
        float wc = (hd2 == 0) ? w0 : (hd2 == 1) ? w1 : w2;
        const __half* row = g_xp1h + (size_t)col * F1 + ch0;
        uint4 ua = *(const uint4*)(row);
        uint4 ub = *(const uint4*)(row + 8);
        uint4 uc = *(const uint4*)(row + 16);
        float2 f;
        f = __half22float2(*(__half2*)&ua.x); acc[0]  += wa * f.x; acc[1]  += wa * f.y;
        f = __half22float2(*(__half2*)&ua.y); acc[2]  += wa * f.x; acc[3]  += wa * f.y;
        f = __half22float2(*(__half2*)&ua.z); acc[4]  += wa * f.x; acc[5]  += wa * f.y;
        f = __half22float2(*(__half2*)&ua.w); acc[6]  += wa * f.x; acc[7]  += wa * f.y;
        f = __half22float2(*(__half2*)&ub.x); acc[8]  += wb * f.x; acc[9]  += wb * f.y;
        f = __half22float2(*(__half2*)&ub.y); acc[10] += wb * f.x; acc[11] += wb * f.y;
        f = __half22float2(*(__half2*)&ub.z); acc[12] += wb * f.x; acc[13] += wb * f.y;
        f = __half22float2(*(__half2*)&ub.w); acc[14] += wb * f.x; acc[15] += wb * f.y;
        f = __half22float2(*(__half2*)&uc.x); acc[16] += wc * f.x; acc[17] += wc * f.y;
        f = __half22float2(*(__half2*)&uc.y); acc[18] += wc * f.x; acc[19] += wc * f.y;
        f = __half22float2(*(__half2*)&uc.z); acc[20] += wc * f.x; acc[21] += wc * f.y;
        f = __half22float2(*(__half2*)&uc.w); acc[22] += wc * f.x; acc[23] += wc * f.y;
    }

    float invv[3];
    invv[0] = (hd0 == 0) ? inv0 : (hd0 == 1) ? inv1 : inv2;
    invv[1] = (hd1 == 0) ? inv0 : (hd1 == 1) ? inv1 : inv2;
    invv[2] = (hd2 == 0) ? inv0 : (hd2 == 1) ? inv1 : inv2;
    __half* outp = g_hh + (size_t)n * F1 + ch0;
    #pragma unroll
    for (int c = 0; c < 3; c++) {
        float inv = invv[c];
        float4 ba = *(const float4*)(b1 + ch0 + c * 8);
        float4 bb = *(const float4*)(b1 + ch0 + c * 8 + 4);
        float o[8];
        o[0] = acc[c*8+0] * inv + ba.x; o[1] = acc[c*8+1] * inv + ba.y;
        o[2] = acc[c*8+2] * inv + ba.z; o[3] = acc[c*8+3] * inv + ba.w;
        o[4] = acc[c*8+4] * inv + bb.x; o[5] = acc[c*8+5] * inv + bb.y;
        o[6] = acc[c*8+6] * inv + bb.z; o[7] = acc[c*8+7] * inv + bb.w;
        #pragma unroll
        for (int i = 0; i < 8; i++)
            o[i] = (o[i] > 0.f) ? o[i] : expm1f(o[i]);
        __half2 h0 = __floats2half2_rn(o[0], o[1]);
        __half2 h1 = __floats2half2_rn(o[2], o[3]);
        __half2 h2 = __floats2half2_rn(o[4], o[5]);
        __half2 h3 = __floats2half2_rn(o[6], o[7]);
        uint4 u;
        u.x = *(uint32_t*)&h0; u.y = *(uint32_t*)&h1;
        u.z = *(uint32_t*)&h2; u.w = *(uint32_t*)&h3;
        *(uint4*)(outp + c * 8) = u;
    }
}

/* ======================================================================== */
/*  Fused softmax + aggregation, layer 2 (1 head). Warp per node.           */
/* ======================================================================== */
__global__ __launch_bounds__(256)
void fused_agg2_kernel(const float* __restrict__ b2, float* __restrict__ out) {
    __shared__ float sw[8][128];
    __shared__ int   scl[8][128];
    int wrp = threadIdx.x >> 5;
    int n = blockIdx.x * 8 + wrp;
    if (n >= N_NODES) return;
    int lane = threadIdx.x & 31;
    int st = g_rowptr[n], en = g_rowptr[n + 1];
    int deg = en - st;

    float ad = g_adst2[n];

    float sum = 0.f;
    #pragma unroll
    for (int r = 0; r < 4; r++) {
        int idx = r * 32 + lane;
        if (idx < deg) {
            int col = g_col[st + idx];
            float v = g_asrc2[col] + ad;
            v = (v > 0.f) ? v : 0.2f * v;
            float e = __expf(v);
            sw[wrp][idx] = e;
            scl[wrp][idx] = col;
            sum += e;
        }
    }
    for (int idx = 128 + lane; idx < deg; idx += 32) {
        int col = g_col[st + idx];
        float v = g_asrc2[col] + ad;
        v = (v > 0.f) ? v : 0.2f * v;
        sum += __expf(v);
    }
    sum = warpSum(sum);
    float inv = 1.f / sum;
    __syncwarp();

    int ch0 = lane * 8;
    float acc[8];
    #pragma unroll
    for (int i = 0; i < 8; i++) acc[i] = 0.f;

    int degf = deg < 128 ? deg : 128;
    for (int idx = 0; idx < degf; idx++) {
        float w  = sw[wrp][idx];
        int  col = scl[wrp][idx];
        uint4 u = *(const uint4*)(g_xp2h + (size_t)col * HID + ch0);
        float2 f0 = __half22float2(*(__half2*)&u.x);
        float2 f1 = __half22float2(*(__half2*)&u.y);
        float2 f2 = __half22float2(*(__half2*)&u.z);
        float2 f3 = __half22float2(*(__half2*)&u.w);
        acc[0] += w * f0.x; acc[1] += w * f0.y;
        acc[2] += w * f1.x; acc[3] += w * f1.y;
        acc[4] += w * f2.x; acc[5] += w * f2.y;
        acc[6] += w * f3.x; acc[7] += w * f3.y;
    }
    for (int idx = 128; idx < deg; idx++) {
        int col = g_col[st + idx];
        float v = g_asrc2[col] + ad;
        v = (v > 0.f) ? v : 0.2f * v;
        float w = __expf(v);
        uint4 u = *(const uint4*)(g_xp2h + (size_t)col * HID + ch0);
        float2 f0 = __half22float2(*(__half2*)&u.x);
        float2 f1 = __half22float2(*(__half2*)&u.y);
        float2 f2 = __half22float2(*(__half2*)&u.z);
        float2 f3 = __half22float2(*(__half2*)&u.w);
        acc[0] += w * f0.x; acc[1] += w * f0.y;
        acc[2] += w * f1.x; acc[3] += w * f1.y;
        acc[4] += w * f2.x; acc[5] += w * f2.y;
        acc[6] += w * f3.x; acc[7] += w * f3.y;
    }

    float4 ba = *(const float4*)(b2 + ch0);
    float4 bb = *(const float4*)(b2 + ch0 + 4);
    float* op = out + (size_t)n * HID + ch0;
    *(float4*)op = make_float4(acc[0] * inv + ba.x, acc[1] * inv + ba.y,
                               acc[2] * inv + ba.z, acc[3] * inv + ba.w);
    *(float4*)(op + 4) = make_float4(acc[4] * inv + bb.x, acc[5] * inv + bb.y,
                                     acc[6] * inv + bb.z, acc[7] * inv + bb.w);
}

/* ---------------- launch --------------------------------------------------- */
extern "C" void kernel_launch(void* const* d_in, const int* in_sizes, int n_in,
                              void* d_out, int out_size) {
    const float* x   = (const float*)d_in[0];
    const void*  ei  = d_in[1];
    const float* W1  = (const float*)d_in[2];
    const float* as1 = (const float*)d_in[3];
    const float* ad1 = (const float*)d_in[4];
    const float* b1  = (const float*)d_in[5];
    const float* W2  = (const float*)d_in[6];
    const float* as2 = (const float*)d_in[7];
    const float* ad2 = (const float*)d_in[8];
    const float* b2  = (const float*)d_in[9];
    float* out = (float*)d_out;

    void *p_x1h, *p_x2h, *p_as1, *p_ad1, *p_as2, *p_ad2;
    void *p_xh, *p_hh, *p_w1h, *p_w2h;
    cudaGetSymbolAddress(&p_x1h, g_xp1h);
    cudaGetSymbolAddress(&p_x2h, g_xp2h);
    cudaGetSymbolAddress(&p_as1, g_asrc1);
    cudaGetSymbolAddress(&p_ad1, g_adst1);
    cudaGetSymbolAddress(&p_as2, g_asrc2);
    cudaGetSymbolAddress(&p_ad2, g_adst2);
    cudaGetSymbolAddress(&p_xh,  gx_h);
    cudaGetSymbolAddress(&p_hh,  g_hh);
    cudaGetSymbolAddress(&p_w1h, gw1t_h);
    cudaGetSymbolAddress(&p_w2h, gw2t_h);

    cudaFuncSetAttribute(mma_gemm_kernel,
                         cudaFuncAttributeMaxDynamicSharedMemorySize, GSMEM);

    /* #1..#3: prerequisites of GEMM1 (W2 transpose rides along in #2) */
    {
        int n4 = N_NODES * IN_DIM / 4;
        conv_half_kernel<<<(n4 + 255) / 256, 256>>>(x, (__half*)p_xh, n4);
        trans_both_kernel<<<dim3(F1 / 32, KDIM / 32, 2), dim3(32, 8)>>>(
            W1, (__half*)p_w1h, W2, (__half*)p_w2h);
    }
    init_kernel<<<NBLK, 256>>>((const int*)ei);

    /* #4: GEMM1 + fused attention, persistent (ncu capture target) */
    {
        int nTilesX = F1 / 128;
        int nTiles  = nTilesX * ((N_NODES + 127) / 128);
        int grid = nTiles < NPERS ? nTiles : NPERS;
        mma_gemm_kernel<<<grid, 256, GSMEM>>>(
            (const __half*)p_xh, (const __half*)p_w1h,
            (__half*)p_x1h, as1, ad1, (float*)p_as1, (float*)p_ad1,
            H1, N_NODES, F1, nTilesX, nTiles);
    }

    /* CSR build (independent of GEMM1) */
    count_kernel<<<(ET + 255) / 256, 256>>>(ei);
    bsum_kernel<<<NBLK, 256>>>();
    bscan_kernel<<<1, 128>>>();
    fscan_kernel<<<NBLK, 256>>>();
    scatter_kernel<<<(ET + 255) / 256, 256>>>(ei);

    /* layer 1 edge phase: fused softmax + aggregation */
    fused_agg1_kernel<<<(N_NODES + 7) / 8, 256>>>(b1);

    /* layer 2 */
    {
        int nTilesX = HID / 128;
        int nTiles  = nTilesX * ((N_NODES + 127) / 128);
        int grid = nTiles < NPERS ? nTiles : NPERS;
        mma_gemm_kernel<<<grid, 256, GSMEM>>>(
            (const __half*)p_hh, (const __half*)p_w2h,
            (__half*)p_x2h, as2, ad2, (float*)p_as2, (float*)p_ad2,
            1, N_NODES, HID, nTilesX, nTiles);
    }
    fused_agg2_kernel<<<(N_NODES + 7) / 8, 256>>>(b2, out);
}

// round 17
// speedup vs baseline: 1.1169x; 1.0615x over previous
#include <cuda_runtime.h>
#include <cuda_fp16.h>
#include <math.h>
#include <stdint.h>

#define N_NODES 20000
#define E_EDGES 320000
#define ET      (E_EDGES + N_NODES)   /* 340000 with self loops */
#define IN_DIM  768
#define HID     256
#define H1      3
#define F1      (H1 * HID)            /* 768 */
#define KDIM    768
#define NBLK    ((N_NODES + 255) / 256)   /* 79 */
#define NPERS   296                   /* 2 CTAs x 148 SMs */

/* ---------------- scratch (device globals, no allocs allowed) ------------- */
__device__ __half g_xp1h[(size_t)N_NODES * F1];    /* GEMM1 out (fp16)   */
__device__ __half g_xp2h[(size_t)N_NODES * HID];   /* GEMM2 out (fp16)   */
__device__ __half gx_h [(size_t)N_NODES * IN_DIM]; /* x in fp16          */
__device__ __half g_hh [(size_t)N_NODES * F1];     /* h in fp16          */
__device__ __half gw1t_h[F1 * KDIM];               /* W1^T [n][k] fp16   */
__device__ __half gw2t_h[HID * KDIM];
__device__ float g_asrc1[N_NODES * H1];
__device__ float g_adst1[N_NODES * H1];
__device__ float g_asrc2[N_NODES];
__device__ float g_adst2[N_NODES];
__device__ int   g_deg[N_NODES];
__device__ int   g_rowptr[N_NODES + 1];
__device__ int   g_cursor[N_NODES];
__device__ int   g_col[ET];
__device__ int   g_bsum[128];
__device__ int   g_boff[128];
__device__ int   g_is64;

/* ---------------- helpers ------------------------------------------------- */
__device__ __forceinline__ float warpSum(float v) {
    #pragma unroll
    for (int o = 16; o; o >>= 1) v += __shfl_xor_sync(0xffffffffu, v, o);
    return v;
}
__device__ __forceinline__ uint32_t smem_u32(const void* p) {
    uint32_t a;
    asm("{ .reg .u64 t; cvta.to.shared.u64 t, %1; cvt.u32.u64 %0, t; }"
        : "=r"(a) : "l"(p));
    return a;
}

/* ---------------- mma.sync / ldmatrix / cp.async wrappers ----------------- */
__device__ __forceinline__ void ldsm_x4(uint32_t* r, uint32_t addr) {
    asm volatile("ldmatrix.sync.aligned.m8n8.x4.shared.b16 {%0,%1,%2,%3}, [%4];"
        : "=r"(r[0]), "=r"(r[1]), "=r"(r[2]), "=r"(r[3]) : "r"(addr));
}
__device__ __forceinline__ void mma_f16(float* c, const uint32_t* a, const uint32_t* b) {
    asm volatile(
        "mma.sync.aligned.m16n8k16.row.col.f32.f16.f16.f32 "
        "{%0,%1,%2,%3}, {%4,%5,%6,%7}, {%8,%9}, {%0,%1,%2,%3};"
        : "+f"(c[0]), "+f"(c[1]), "+f"(c[2]), "+f"(c[3])
        : "r"(a[0]), "r"(a[1]), "r"(a[2]), "r"(a[3]), "r"(b[0]), "r"(b[1]));
}
__device__ __forceinline__ void cp16(uint32_t dst, const void* src, int sz) {
    asm volatile("cp.async.cg.shared.global [%0], [%1], 16, %2;"
        :: "r"(dst), "l"(src), "r"(sz) : "memory");
}
__device__ __forceinline__ void cp_commit() {
    asm volatile("cp.async.commit_group;" ::: "memory");
}
template <int W> __device__ __forceinline__ void cp_wait() {
    asm volatile("cp.async.wait_group %0;" :: "n"(W) : "memory");
}

/* ======================================================================== */
/*  Persistent HMMA GEMM (fp16): Ch[M,N] = A[M,768] @ Bt[N,768]^T            */
/*  CTA tile 128x128, BK=64, 3-stage cp.async, 1 barrier/chunk, ldsm_x4      */
/*  Fused attention dot-product epilogue (atomics)    [R13 configuration]    */
/* ======================================================================== */
#define BK    64
#define LDA   72                   /* 144 B rows: bank stride 4 mod 32 */
#define TILE_AB (128 * LDA * 2)    /* 18432 B per tile array */
#define STG_B  (2 * TILE_AB)       /* 36864 B per stage (A + B) */
#define NSTG   3
#define GSMEM  (NSTG * STG_B)      /* 110592 B */
#define NCHUNK (KDIM / BK)         /* 12 */

__global__ __launch_bounds__(256, 2)
void mma_gemm_kernel(const __half* __restrict__ Ah,
                     const __half* __restrict__ Bh,
                     __half* __restrict__ Ch,
                     const float* __restrict__ att_s,
                     const float* __restrict__ att_d,
                     float* __restrict__ asrc,
                     float* __restrict__ adst,
                     int H, int M, int N, int nTilesX, int nTiles) {
    extern __shared__ char smem[];
    const int t = threadIdx.x, lane = t & 31, wid = t >> 5;
    const int wm = wid >> 2, wn = wid & 3;
    const uint32_t sb = smem_u32(smem);

    const int rbase = t >> 3;            /* 0..31 */
    const int cs    = (t & 7) * 8;       /* fp16 col offset, 0..56 */
    const uint32_t dd = (uint32_t)(rbase * LDA + cs) * 2;
    const int g = lane >> 2, tq = lane & 3;

    for (int tile = blockIdx.x; tile < nTiles; tile += gridDim.x) {
        const int rowBase = (tile / nTilesX) * 128;
        const int colBase = (tile % nTilesX) * 128;

        int av[4];
        #pragma unroll
        for (int i = 0; i < 4; i++)
            av[i] = (rowBase + rbase + 32 * i) < M ? 16 : 0;
        const __half* pA = Ah + (size_t)(rowBase + rbase) * KDIM + cs;
        const __half* pB = Bh + (size_t)(colBase + rbase) * KDIM + cs;

        float acc[4][4][4];
        #pragma unroll
        for (int i = 0; i < 4; i++)
            #pragma unroll
            for (int j = 0; j < 4; j++)
                #pragma unroll
                for (int q = 0; q < 4; q++) acc[i][j][q] = 0.f;

        /* prologue: chunks 0,1 -> stages 0,1 */
        #pragma unroll
        for (int p = 0; p < 2; p++) {
            const uint32_t b = sb + p * STG_B;
            const int k0 = p * BK;
            #pragma unroll
            for (int i = 0; i < 4; i++) {
                cp16(b + dd + i * (32 * LDA * 2), pA + k0 + (size_t)(32 * i) * KDIM, av[i]);
                cp16(b + TILE_AB + dd + i * (32 * LDA * 2), pB + k0 + (size_t)(32 * i) * KDIM, 16);
            }
            cp_commit();
        }

        for (int c = 0; c < NCHUNK; c++) {
            if (c < NCHUNK - 1) cp_wait<1>();
            else                cp_wait<0>();
            __syncthreads();

            if (c + 2 < NCHUNK) {
                const int k0 = (c + 2) * BK;
                const uint32_t b = sb + ((c + 2) % NSTG) * STG_B;
                #pragma unroll
                for (int i = 0; i < 4; i++) {
                    cp16(b + dd + i * (32 * LDA * 2), pA + k0 + (size_t)(32 * i) * KDIM, av[i]);
                    cp16(b + TILE_AB + dd + i * (32 * LDA * 2), pB + k0 + (size_t)(32 * i) * KDIM, 16);
                }
                cp_commit();
            }

            const uint32_t sA = sb + (c % NSTG) * STG_B;
            const uint32_t sB = sA + TILE_AB;

            #pragma unroll
            for (int ks = 0; ks < 4; ks++) {
                const int kk = ks * 16;
                uint32_t ah[4][4];
                {
                    const int r  = wm * 64 + (lane & 15);
                    const int kc = kk + ((lane >> 4) << 3);
                    #pragma unroll
                    for (int mt = 0; mt < 4; mt++)
                        ldsm_x4(ah[mt], sA + (uint32_t)((r + mt * 16) * LDA + kc) * 2);
                }
                #pragma unroll
                for (int p = 0; p < 2; p++) {
                    uint32_t bb[4];
                    const int row = wn * 32 + p * 16 + ((lane >> 4) << 3) + (lane & 7);
                    const int kc  = kk + (((lane >> 3) & 1) << 3);
                    ldsm_x4(bb, sB + (uint32_t)(row * LDA + kc) * 2);
                    #pragma unroll
                    for (int mt = 0; mt < 4; mt++) {
                        mma_f16(acc[mt][2 * p],     ah[mt], bb);
                        mma_f16(acc[mt][2 * p + 1], ah[mt], bb + 2);
                    }
                }
            }
        }

        /* ---- epilogue: fp16 store + fused attention dot products --------- */
        const int h = (H > 1) ? (colBase >> 8) : 0;

        float s_c[8], d_c[8];
        #pragma unroll
        for (int nt = 0; nt < 4; nt++) {
            int colg = colBase + wn * 32 + nt * 8 + 2 * tq;
            s_c[2 * nt]     = att_s[colg];
            s_c[2 * nt + 1] = att_s[colg + 1];
            d_c[2 * nt]     = att_d[colg];
            d_c[2 * nt + 1] = att_d[colg + 1];
        }

        #pragma unroll
        for (int mt = 0; mt < 4; mt++) {
            int r0g = rowBase + wm * 64 + mt * 16 + g;
            float ps0 = 0.f, pd0 = 0.f, ps1 = 0.f, pd1 = 0.f;
            #pragma unroll
            for (int nt = 0; nt < 4; nt++) {
                int col = colBase + wn * 32 + nt * 8 + 2 * tq;
                if (r0g < M)
                    *(__half2*)&Ch[(size_t)r0g * N + col] =
                        __floats2half2_rn(acc[mt][nt][0], acc[mt][nt][1]);
                if (r0g + 8 < M)
                    *(__half2*)&Ch[(size_t)(r0g + 8) * N + col] =
                        __floats2half2_rn(acc[mt][nt][2], acc[mt][nt][3]);
                ps0 += acc[mt][nt][0] * s_c[2 * nt] + acc[mt][nt][1] * s_c[2 * nt + 1];
                pd0 += acc[mt][nt][0] * d_c[2 * nt] + acc[mt][nt][1] * d_c[2 * nt + 1];
                ps1 += acc[mt][nt][2] * s_c[2 * nt] + acc[mt][nt][3] * s_c[2 * nt + 1];
                pd1 += acc[mt][nt][2] * d_c[2 * nt] + acc[mt][nt][3] * d_c[2 * nt + 1];
            }
            #pragma unroll
            for (int o = 1; o <= 2; o <<= 1) {
                ps0 += __shfl_xor_sync(0xffffffffu, ps0, o);
                pd0 += __shfl_xor_sync(0xffffffffu, pd0, o);
                ps1 += __shfl_xor_sync(0xffffffffu, ps1, o);
                pd1 += __shfl_xor_sync(0xffffffffu, pd1, o);
            }
            if (tq == 0) {
                if (r0g < M) {
                    atomicAdd(&asrc[r0g * H + h], ps0);
                    atomicAdd(&adst[r0g * H + h], pd0);
                }
                if (r0g + 8 < M) {
                    atomicAdd(&asrc[(r0g + 8) * H + h], ps1);
                    atomicAdd(&adst[(r0g + 8) * H + h], pd1);
                }
            }
        }
    }
}

/* ---------------- fp32 -> fp16 elementwise --------------------------------- */
__global__ void conv_half_kernel(const float* __restrict__ src,
                                 __half* __restrict__ dst, int n4) {
    int i = blockIdx.x * blockDim.x + threadIdx.x;
    if (i >= n4) return;
    float4 v = ((const float4*)src)[i];
    __half2 a = __floats2half2_rn(v.x, v.y);
    __half2 b = __floats2half2_rn(v.z, v.w);
    ((uint2*)dst)[i] = make_uint2(*(uint32_t*)&a, *(uint32_t*)&b);
}

/* ---------------- W1 and W2 transpose -> fp16, single launch --------------- */
__global__ void trans_both_kernel(const float* __restrict__ W1f, __half* __restrict__ T1,
                                  const float* __restrict__ W2f, __half* __restrict__ T2) {
    __shared__ float tile[32][33];
    const float* W;
    __half* T;
    int N;
    if (blockIdx.z == 0) { W = W1f; T = T1; N = F1; }
    else                 { W = W2f; T = T2; N = HID; }
    int n0 = blockIdx.x * 32;
    if (n0 >= N) return;
    int k0 = blockIdx.y * 32;
    int tx = threadIdx.x, ty = threadIdx.y;   /* 32 x 8 */
    #pragma unroll
    for (int i = 0; i < 32; i += 8)
        tile[ty + i][tx] = W[(size_t)(k0 + ty + i) * N + n0 + tx];
    __syncthreads();
    #pragma unroll
    for (int i = 0; i < 32; i += 8) {
        float v = tile[tx][ty + i];
        T[(size_t)(n0 + ty + i) * KDIM + k0 + tx] = __float2half_rn(v);
    }
}

/* ---------------- init: zero deg + att accumulators + detect dtype --------- */
__global__ void init_kernel(const int* ei32) {
    int i = blockIdx.x * 256 + threadIdx.x;
    if (i < N_NODES) g_deg[i] = 0;
    for (int j = i; j < N_NODES * H1; j += NBLK * 256) {
        g_asrc1[j] = 0.f;
        g_adst1[j] = 0.f;
    }
    if (i < N_NODES) {
        g_asrc2[i] = 0.f;
        g_adst2[i] = 0.f;
    }
    if (blockIdx.x == 0) {
        __shared__ int any;
        if (threadIdx.x == 0) any = 0;
        __syncthreads();
        int v = 0;
        for (int j = threadIdx.x; j < 1024; j += 256)
            v |= ei32[2 * j + 1];
        if (v) atomicOr(&any, 1);
        __syncthreads();
        if (threadIdx.x == 0) g_is64 = (any == 0) ? 1 : 0;
    }
}
__device__ __forceinline__ int edge_at(const void* ei, long long idx) {
    if (g_is64) return (int)((const long long*)ei)[idx];
    return ((const int*)ei)[idx];
}

/* ---------------- CSR build ------------------------------------------------ */
__global__ void count_kernel(const void* ei) {
    int e = blockIdx.x * blockDim.x + threadIdx.x;
    if (e >= ET) return;
    int d = (e < E_EDGES) ? edge_at(ei, (long long)E_EDGES + e) : (e - E_EDGES);
    atomicAdd(&g_deg[d], 1);
}
__global__ void bsum_kernel() {
    __shared__ int s[256];
    int i = blockIdx.x * 256 + threadIdx.x;
    s[threadIdx.x] = (i < N_NODES) ? g_deg[i] : 0;
    __syncthreads();
    for (int o = 128; o; o >>= 1) {
        if (threadIdx.x < o) s[threadIdx.x] += s[threadIdx.x + o];
        __syncthreads();
    }
    if (threadIdx.x == 0) g_bsum[blockIdx.x] = s[0];
}
__global__ void bscan_kernel() {
    __shared__ int s[128];
    int t = threadIdx.x;
    int v = (t < NBLK) ? g_bsum[t] : 0;
    s[t] = v;
    __syncthreads();
    for (int o = 1; o < 128; o <<= 1) {
        int u = (t >= o) ? s[t - o] : 0;
        __syncthreads();
        s[t] += u;
        __syncthreads();
    }
    g_boff[t] = s[t] - v;
    if (t == 0) g_rowptr[N_NODES] = ET;
}
__global__ void fscan_kernel() {
    __shared__ int s[256];
    int t = threadIdx.x;
    int i = blockIdx.x * 256 + t;
    int d = (i < N_NODES) ? g_deg[i] : 0;
    s[t] = d;
    __syncthreads();
    for (int o = 1; o < 256; o <<= 1) {
        int u = (t >= o) ? s[t - o] : 0;
        __syncthreads();
        s[t] += u;
        __syncthreads();
    }
    if (i < N_NODES) {
        int off = s[t] - d + g_boff[blockIdx.x];
        g_rowptr[i] = off;
        g_cursor[i] = off;
    }
}
__global__ void scatter_kernel(const void* ei) {
    int e = blockIdx.x * blockDim.x + threadIdx.x;
    if (e >= ET) return;
    int s, d;
    if (e < E_EDGES) {
        s = edge_at(ei, e);
        d = edge_at(ei, (long long)E_EDGES + e);
    } else {
        s = d = e - E_EDGES;
    }
    int slot = atomicAdd(&g_cursor[d], 1);
    g_col[slot] = s;
}

/* ======================================================================== */
/*  Fused softmax + aggregation, layer 1 (3 heads). Warp per node.          */
/* ======================================================================== */
__global__ __launch_bounds__(256)
void fused_agg1_kernel(const float* __restrict__ b1) {
    __shared__ float sw0[8][128];
    __shared__ float sw1[8][128];
    __shared__ float sw2[8][128];
    __shared__ int   scl[8][128];
    int wrp = threadIdx.x >> 5;
    int n = blockIdx.x * 8 + wrp;
    if (n >= N_NODES) return;
    int lane = threadIdx.x & 31;
    int st = g_rowptr[n], en = g_rowptr[n + 1];
    int deg = en - st;

    float ad0 = g_adst1[n * 3 + 0];
    float ad1 = g_adst1[n * 3 + 1];
    float ad2 = g_adst1[n * 3 + 2];

    float s0 = 0.f, s1 = 0.f, s2 = 0.f;
    #pragma unroll
    for (int r = 0; r < 4; r++) {
        int idx = r * 32 + lane;
        if (idx < deg) {
            int col = g_col[st + idx];
            float v0 = g_asrc1[col * 3 + 0] + ad0;
            float v1 = g_asrc1[col * 3 + 1] + ad1;
            float v2 = g_asrc1[col * 3 + 2] + ad2;
            v0 = (v0 > 0.f) ? v0 : 0.2f * v0;
            v1 = (v1 > 0.f) ? v1 : 0.2f * v1;
            v2 = (v2 > 0.f) ? v2 : 0.2f * v2;
            float e0 = __expf(v0), e1 = __expf(v1), e2 = __expf(v2);
            sw0[wrp][idx] = e0;
            sw1[wrp][idx] = e1;
            sw2[wrp][idx] = e2;
            scl[wrp][idx] = col;
            s0 += e0; s1 += e1; s2 += e2;
        }
    }
    for (int idx = 128 + lane; idx < deg; idx += 32) {
        int col = g_col[st + idx];
        float v0 = g_asrc1[col * 3 + 0] + ad0;
        float v1 = g_asrc1[col * 3 + 1] + ad1;
        float v2 = g_asrc1[col * 3 + 2] + ad2;
        v0 = (v0 > 0.f) ? v0 : 0.2f * v0;
        v1 = (v1 > 0.f) ? v1 : 0.2f * v1;
        v2 = (v2 > 0.f) ? v2 : 0.2f * v2;
        s0 += __expf(v0); s1 += __expf(v1); s2 += __expf(v2);
    }
    s0 = warpSum(s0); s1 = warpSum(s1); s2 = warpSum(s2);
    float inv0 = 1.f / s0, inv1 = 1.f / s1, inv2 = 1.f / s2;
    __syncwarp();

    int ch0 = lane * 24;
    int hd0 = ch0 >> 8, hd1 = (ch0 + 8) >> 8, hd2 = (ch0 + 16) >> 8;

    float acc[24];
    #pragma unroll
    for (int i = 0; i < 24; i++) acc[i] = 0.f;

    int degf = deg < 128 ? deg : 128;
    for (int idx = 0; idx < degf; idx++) {
        float w0 = sw0[wrp][idx];
        float w1 = sw1[wrp][idx];
        float w2 = sw2[wrp][idx];
        int  col = scl[wrp][idx];
        float wa = (hd0 == 0) ? w0 : (hd0 == 1) ? w1 : w2;
        float wb = (hd1 == 0) ? w0 : (hd1 == 1) ? w1 : w2;
        float wc = (hd2 == 0) ? w0 : (hd2 == 1) ? w1 : w2;
        const __half* row = g_xp1h + (size_t)col * F1 + ch0;
        uint4 ua = *(const uint4*)(row);
        uint4 ub = *(const uint4*)(row + 8);
        uint4 uc = *(const uint4*)(row + 16);
        float2 f;
        f = __half22float2(*(__half2*)&ua.x); acc[0]  += wa * f.x; acc[1]  += wa * f.y;
        f = __half22float2(*(__half2*)&ua.y); acc[2]  += wa * f.x; acc[3]  += wa * f.y;
        f = __half22float2(*(__half2*)&ua.z); acc[4]  += wa * f.x; acc[5]  += wa * f.y;
        f = __half22float2(*(__half2*)&ua.w); acc[6]  += wa * f.x; acc[7]  += wa * f.y;
        f = __half22float2(*(__half2*)&ub.x); acc[8]  += wb * f.x; acc[9]  += wb * f.y;
        f = __half22float2(*(__half2*)&ub.y); acc[10] += wb * f.x; acc[11] += wb * f.y;
        f = __half22float2(*(__half2*)&ub.z); acc[12] += wb * f.x; acc[13] += wb * f.y;
        f = __half22float2(*(__half2*)&ub.w); acc[14] += wb * f.x; acc[15] += wb * f.y;
        f = __half22float2(*(__half2*)&uc.x); acc[16] += wc * f.x; acc[17] += wc * f.y;
        f = __half22float2(*(__half2*)&uc.y); acc[18] += wc * f.x; acc[19] += wc * f.y;
        f = __half22float2(*(__half2*)&uc.z); acc[20] += wc * f.x; acc[21] += wc * f.y;
        f = __half22float2(*(__half2*)&uc.w); acc[22] += wc * f.x; acc[23] += wc * f.y;
    }
    for (int idx = 128; idx < deg; idx++) {
        int col = g_col[st + idx];
        float v0 = g_asrc1[col * 3 + 0] + ad0;
        float v1 = g_asrc1[col * 3 + 1] + ad1;
        float v2 = g_asrc1[col * 3 + 2] + ad2;
        v0 = (v0 > 0.f) ? v0 : 0.2f * v0;
        v1 = (v1 > 0.f) ? v1 : 0.2f * v1;
        v2 = (v2 > 0.f) ? v2 : 0.2f * v2;
        float w0 = __expf(v0), w1 = __expf(v1), w2 = __expf(v2);
        float wa = (hd0 == 0) ? w0 : (hd0 == 1) ? w1 : w2;
        float wb = (hd1 == 0) ? w0 : (hd1 == 1) ? w1 : w2;
        float wc = (hd2 == 0) ? w0 : (hd2 == 1) ? w1 : w2;
        const __half* row = g_xp1h + (size_t)col * F1 + ch0;
        uint4 ua = *(const uint4*)(row);
        uint4 ub = *(const uint4*)(row + 8);
        uint4 uc = *(const uint4*)(row + 16);
        float2 f;
        f = __half22float2(*(__half2*)&ua.x); acc[0]  += wa * f.x; acc[1]  += wa * f.y;
        f = __half22float2(*(__half2*)&ua.y); acc[2]  += wa * f.x; acc[3]  += wa * f.y;
        f = __half22float2(*(__half2*)&ua.z); acc[4]  += wa * f.x; acc[5]  += wa * f.y;
        f = __half22float2(*(__half2*)&ua.w); acc[6]  += wa * f.x; acc[7]  += wa * f.y;
        f = __half22float2(*(__half2*)&ub.x); acc[8]  += wb * f.x; acc[9]  += wb * f.y;
        f = __half22float2(*(__half2*)&ub.y); acc[10] += wb * f.x; acc[11] += wb * f.y;
        f = __half22float2(*(__half2*)&ub.z); acc[12] += wb * f.x; acc[13] += wb * f.y;
        f = __half22float2(*(__half2*)&ub.w); acc[14] += wb * f.x; acc[15] += wb * f.y;
        f = __half22float2(*(__half2*)&uc.x); acc[16] += wc * f.x; acc[17] += wc * f.y;
        f = __half22float2(*(__half2*)&uc.y); acc[18] += wc * f.x; acc[19] += wc * f.y;
        f = __half22float2(*(__half2*)&uc.z); acc[20] += wc * f.x; acc[21] += wc * f.y;
        f = __half22float2(*(__half2*)&uc.w); acc[22] += wc * f.x; acc[23] += wc * f.y;
    }

    float invv[3];
    invv[0] = (hd0 == 0) ? inv0 : (hd0 == 1) ? inv1 : inv2;
    invv[1] = (hd1 == 0) ? inv0 : (hd1 == 1) ? inv1 : inv2;
    invv[2] = (hd2 == 0) ? inv0 : (hd2 == 1) ? inv1 : inv2;
    __half* outp = g_hh + (size_t)n * F1 + ch0;
    #pragma unroll
    for (int c = 0; c < 3; c++) {
        float inv = invv[c];
        float4 ba = *(const float4*)(b1 + ch0 + c * 8);
        float4 bb = *(const float4*)(b1 + ch0 + c * 8 + 4);
        float o[8];
        o[0] = acc[c*8+0] * inv + ba.x; o[1] = acc[c*8+1] * inv + ba.y;
        o[2] = acc[c*8+2] * inv + ba.z; o[3] = acc[c*8+3] * inv + ba.w;
        o[4] = acc[c*8+4] * inv + bb.x; o[5] = acc[c*8+5] * inv + bb.y;
        o[6] = acc[c*8+6] * inv + bb.z; o[7] = acc[c*8+7] * inv + bb.w;
        #pragma unroll
        for (int i = 0; i < 8; i++)
            o[i] = (o[i] > 0.f) ? o[i] : expm1f(o[i]);
        __half2 h0 = __floats2half2_rn(o[0], o[1]);
        __half2 h1 = __floats2half2_rn(o[2], o[3]);
        __half2 h2 = __floats2half2_rn(o[4], o[5]);
        __half2 h3 = __floats2half2_rn(o[6], o[7]);
        uint4 u;
        u.x = *(uint32_t*)&h0; u.y = *(uint32_t*)&h1;
        u.z = *(uint32_t*)&h2; u.w = *(uint32_t*)&h3;
        *(uint4*)(outp + c * 8) = u;
    }
}

/* ======================================================================== */
/*  Fused softmax + aggregation, layer 2 (1 head). Warp per node.           */
/* ======================================================================== */
__global__ __launch_bounds__(256)
void fused_agg2_kernel(const float* __restrict__ b2, float* __restrict__ out) {
    __shared__ float sw[8][128];
    __shared__ int   scl[8][128];
    int wrp = threadIdx.x >> 5;
    int n = blockIdx.x * 8 + wrp;
    if (n >= N_NODES) return;
    int lane = threadIdx.x & 31;
    int st = g_rowptr[n], en = g_rowptr[n + 1];
    int deg = en - st;

    float ad = g_adst2[n];

    float sum = 0.f;
    #pragma unroll
    for (int r = 0; r < 4; r++) {
        int idx = r * 32 + lane;
        if (idx < deg) {
            int col = g_col[st + idx];
            float v = g_asrc2[col] + ad;
            v = (v > 0.f) ? v : 0.2f * v;
            float e = __expf(v);
            sw[wrp][idx] = e;
            scl[wrp][idx] = col;
            sum += e;
        }
    }
    for (int idx = 128 + lane; idx < deg; idx += 32) {
        int col = g_col[st + idx];
        float v = g_asrc2[col] + ad;
        v = (v > 0.f) ? v : 0.2f * v;
        sum += __expf(v);
    }
    sum = warpSum(sum);
    float inv = 1.f / sum;
    __syncwarp();

    int ch0 = lane * 8;
    float acc[8];
    #pragma unroll
    for (int i = 0; i < 8; i++) acc[i] = 0.f;

    int degf = deg < 128 ? deg : 128;
    for (int idx = 0; idx < degf; idx++) {
        float w  = sw[wrp][idx];
        int  col = scl[wrp][idx];
        uint4 u = *(const uint4*)(g_xp2h + (size_t)col * HID + ch0);
        float2 f0 = __half22float2(*(__half2*)&u.x);
        float2 f1 = __half22float2(*(__half2*)&u.y);
        float2 f2 = __half22float2(*(__half2*)&u.z);
        float2 f3 = __half22float2(*(__half2*)&u.w);
        acc[0] += w * f0.x; acc[1] += w * f0.y;
        acc[2] += w * f1.x; acc[3] += w * f1.y;
        acc[4] += w * f2.x; acc[5] += w * f2.y;
        acc[6] += w * f3.x; acc[7] += w * f3.y;
    }
    for (int idx = 128; idx < deg; idx++) {
        int col = g_col[st + idx];
        float v = g_asrc2[col] + ad;
        v = (v > 0.f) ? v : 0.2f * v;
        float w = __expf(v);
        uint4 u = *(const uint4*)(g_xp2h + (size_t)col * HID + ch0);
        float2 f0 = __half22float2(*(__half2*)&u.x);
        float2 f1 = __half22float2(*(__half2*)&u.y);
        float2 f2 = __half22float2(*(__half2*)&u.z);
        float2 f3 = __half22float2(*(__half2*)&u.w);
        acc[0] += w * f0.x; acc[1] += w * f0.y;
        acc[2] += w * f1.x; acc[3] += w * f1.y;
        acc[4] += w * f2.x; acc[5] += w * f2.y;
        acc[6] += w * f3.x; acc[7] += w * f3.y;
    }

    float4 ba = *(const float4*)(b2 + ch0);
    float4 bb = *(const float4*)(b2 + ch0 + 4);
    float* op = out + (size_t)n * HID + ch0;
    *(float4*)op = make_float4(acc[0] * inv + ba.x, acc[1] * inv + ba.y,
                               acc[2] * inv + ba.z, acc[3] * inv + ba.w);
    *(float4*)(op + 4) = make_float4(acc[4] * inv + bb.x, acc[5] * inv + bb.y,
                                     acc[6] * inv + bb.z, acc[7] * inv + bb.w);
}

/* ---------------- launch --------------------------------------------------- */
extern "C" void kernel_launch(void* const* d_in, const int* in_sizes, int n_in,
                              void* d_out, int out_size) {
    const float* x   = (const float*)d_in[0];
    const void*  ei  = d_in[1];
    const float* W1  = (const float*)d_in[2];
    const float* as1 = (const float*)d_in[3];
    const float* ad1 = (const float*)d_in[4];
    const float* b1  = (const float*)d_in[5];
    const float* W2  = (const float*)d_in[6];
    const float* as2 = (const float*)d_in[7];
    const float* ad2 = (const float*)d_in[8];
    const float* b2  = (const float*)d_in[9];
    float* out = (float*)d_out;

    void *p_x1h, *p_x2h, *p_as1, *p_ad1, *p_as2, *p_ad2;
    void *p_xh, *p_hh, *p_w1h, *p_w2h;
    cudaGetSymbolAddress(&p_x1h, g_xp1h);
    cudaGetSymbolAddress(&p_x2h, g_xp2h);
    cudaGetSymbolAddress(&p_as1, g_asrc1);
    cudaGetSymbolAddress(&p_ad1, g_adst1);
    cudaGetSymbolAddress(&p_as2, g_asrc2);
    cudaGetSymbolAddress(&p_ad2, g_adst2);
    cudaGetSymbolAddress(&p_xh,  gx_h);
    cudaGetSymbolAddress(&p_hh,  g_hh);
    cudaGetSymbolAddress(&p_w1h, gw1t_h);
    cudaGetSymbolAddress(&p_w2h, gw2t_h);

    cudaFuncSetAttribute(mma_gemm_kernel,
                         cudaFuncAttributeMaxDynamicSharedMemorySize, GSMEM);

    /* fork-join: CSR build on a side stream, hidden under GEMM1.
       Host-side stream/event objects only (no device memory); leaked
       intentionally — kernel_launch runs only a handful of times pre-capture. */
    cudaStream_t s2;
    cudaEvent_t evStart, evInit, evCsr;
    cudaStreamCreateWithFlags(&s2, cudaStreamNonBlocking);
    cudaEventCreateWithFlags(&evStart, cudaEventDisableTiming);
    cudaEventCreateWithFlags(&evInit,  cudaEventDisableTiming);
    cudaEventCreateWithFlags(&evCsr,   cudaEventDisableTiming);

    /* fork */
    cudaEventRecord(evStart, 0);
    cudaStreamWaitEvent(s2, evStart, 0);

    /* side stream: init + CSR build */
    init_kernel<<<NBLK, 256, 0, s2>>>((const int*)ei);
    cudaEventRecord(evInit, s2);
    count_kernel<<<(ET + 255) / 256, 256, 0, s2>>>(ei);
    bsum_kernel<<<NBLK, 256, 0, s2>>>();
    bscan_kernel<<<1, 128, 0, s2>>>();
    fscan_kernel<<<NBLK, 256, 0, s2>>>();
    scatter_kernel<<<(ET + 255) / 256, 256, 0, s2>>>(ei);
    cudaEventRecord(evCsr, s2);

    /* main stream: conversions (independent of init) */
    {
        int n4 = N_NODES * IN_DIM / 4;
        conv_half_kernel<<<(n4 + 255) / 256, 256>>>(x, (__half*)p_xh, n4);
        trans_both_kernel<<<dim3(F1 / 32, KDIM / 32, 2), dim3(32, 8)>>>(
            W1, (__half*)p_w1h, W2, (__half*)p_w2h);
    }

    /* GEMM1 needs init (epilogue atomics target zeroed accumulators) */
    cudaStreamWaitEvent(0, evInit, 0);
    {
        int nTilesX = F1 / 128;
        int nTiles  = nTilesX * ((N_NODES + 127) / 128);
        int grid = nTiles < NPERS ? nTiles : NPERS;
        mma_gemm_kernel<<<grid, 256, GSMEM>>>(
            (const __half*)p_xh, (const __half*)p_w1h,
            (__half*)p_x1h, as1, ad1, (float*)p_as1, (float*)p_ad1,
            H1, N_NODES, F1, nTilesX, nTiles);
    }

    /* join: agg1 needs the CSR */
    cudaStreamWaitEvent(0, evCsr, 0);
    fused_agg1_kernel<<<(N_NODES + 7) / 8, 256>>>(b1);

    /* layer 2 */
    {
        int nTilesX = HID / 128;
        int nTiles  = nTilesX * ((N_NODES + 127) / 128);
        int grid = nTiles < NPERS ? nTiles : NPERS;
        mma_gemm_kernel<<<grid, 256, GSMEM>>>(
            (const __half*)p_hh, (const __half*)p_w2h,
            (__half*)p_x2h, as2, ad2, (float*)p_as2, (float*)p_ad2,
            1, N_NODES, HID, nTilesX, nTiles);
    }
    fused_agg2_kernel<<<(N_NODES + 7) / 8, 256>>>(b2, out);
}